// round 7
// baseline (speedup 1.0000x reference)
#include <cuda_runtime.h>
#include <math.h>

#define NA 1614

// ---- static device scratch (no allocations allowed) ----
__device__ float g_bbwt[3072 * 2048];
__device__ float g_raw [3136 * 2048];
__device__ float g_w1t [18432 * 128];
__device__ float g_y1p [8 * 3136 * 128];
__device__ float g_y1  [3136 * 128];
__device__ float g_w2t [1152 * 128];
__device__ float g_w3t [1152 * 128];
__device__ float g_y2  [16 * 49 * 128];
__device__ float g_y3  [16 * 16 * 128];
__device__ float g_rpn [16 * NA];
__device__ int   g_top [64];
__device__ float g_abar[64 * 3072];
__device__ float g_pfp [8 * 64 * 2048];
__device__ float g_pf  [64 * 2048];
__device__ float g_rf  [16 * 2048];

// ---- weight repacks ----
__global__ void k_transpose_bbw(const float* __restrict__ src) {
    // [2048][3072] -> [3072][2048]
    __shared__ float tile[32][33];
    int c0 = blockIdx.x * 32, r0 = blockIdx.y * 32;
    int tx = threadIdx.x, ty = threadIdx.y;
    for (int i = ty; i < 32; i += 8)
        tile[i][tx] = src[(size_t)(r0 + i) * 3072 + c0 + tx];
    __syncthreads();
    for (int i = ty; i < 32; i += 8)
        g_bbwt[(size_t)(c0 + i) * 2048 + r0 + tx] = tile[tx][i];
}
__global__ void k_repack_w1(const float* __restrict__ src) {
    // [128][2048][3][3] -> [(u*2048+c)][o]
    int gid = blockIdx.x * 256 + threadIdx.x;
    int k = gid >> 7, o = gid & 127, u = k >> 11, c = k & 2047;
    g_w1t[gid] = src[(size_t)(o * 2048 + c) * 9 + u];
}
__global__ void k_repack_w2(const float* __restrict__ src) {
    int gid = blockIdx.x * 256 + threadIdx.x;
    int k = gid >> 7, o = gid & 127, u = k >> 7, c = k & 127;
    g_w2t[gid] = src[(o * 128 + c) * 9 + u];
}
__global__ void k_repack_w3(const float* __restrict__ src) {
    int gid = blockIdx.x * 256 + threadIdx.x;
    int k = gid >> 7, o = gid & 127, u = k >> 7, c = k & 127;
    g_w3t[gid] = src[(o * 128 + c) * 9 + u];
}

// ---- shared GEMM inner product: 64x128 tile, 256 thr, 4x8 per thread ----
__device__ __forceinline__ void mac_tile(const float* As, const float* Bs,
                                         float acc[4][8], int ty, int tx) {
#pragma unroll
    for (int kk = 0; kk < 32; kk++) {
        float a0 = As[kk * 65 + ty * 4 + 0];
        float a1 = As[kk * 65 + ty * 4 + 1];
        float a2 = As[kk * 65 + ty * 4 + 2];
        float a3 = As[kk * 65 + ty * 4 + 3];
        float4 b0 = *(const float4*)&Bs[kk * 128 + tx * 8];
        float4 b1 = *(const float4*)&Bs[kk * 128 + tx * 8 + 4];
        float bv[8] = {b0.x, b0.y, b0.z, b0.w, b1.x, b1.y, b1.z, b1.w};
#pragma unroll
        for (int j = 0; j < 8; j++) {
            acc[0][j] += a0 * bv[j];
            acc[1][j] += a1 * bv[j];
            acc[2][j] += a2 * bv[j];
            acc[3][j] += a3 * bv[j];
        }
    }
}

// ---- GEMM1: raw = patchGEMM(x) @ bbwt + b.  M=3136 K=3072 N=2048 ----
__global__ __launch_bounds__(256, 3) void k_gemm_raw(const float* __restrict__ x,
                                                     const float* __restrict__ bias) {
    __shared__ float As[32 * 65];
    __shared__ float Bs[32 * 128];
    const int tid = threadIdx.x;
    const int m0 = blockIdx.x * 64, n0 = blockIdx.y * 128;
    const int kl = tid & 31, mr = tid >> 5;
    const int ty = tid >> 4, tx = tid & 15;
    int pbase[8];
#pragma unroll
    for (int l = 0; l < 8; l++) {
        int m = m0 + mr + l * 8;
        int b = m / 196, p = m - b * 196, i = p / 14, j = p - i * 14;
        pbase[l] = b * 602112 + i * 14336 + j * 32 + kl;
    }
    float acc[4][8];
#pragma unroll
    for (int a = 0; a < 4; a++)
#pragma unroll
        for (int q = 0; q < 8; q++) acc[a][q] = 0.f;
    for (int kt = 0; kt < 96; kt++) {
        int koff = (kt >> 5) * 200704 + (kt & 31) * 448; // c*448*448 + r*448
#pragma unroll
        for (int l = 0; l < 8; l++)
            As[kl * 65 + mr + l * 8] = __ldg(&x[pbase[l] + koff]);
        const float* bsrc = g_bbwt + (size_t)kt * 65536 + n0;
#pragma unroll
        for (int l = 0; l < 16; l++) {
            int e = tid + l * 256;
            Bs[e] = bsrc[(e >> 7) * 2048 + (e & 127)];
        }
        __syncthreads();
        mac_tile(As, Bs, acc, ty, tx);
        __syncthreads();
    }
#pragma unroll
    for (int im = 0; im < 4; im++) {
        float* dst = g_raw + (size_t)(m0 + ty * 4 + im) * 2048 + n0 + tx * 8;
#pragma unroll
        for (int jn = 0; jn < 8; jn++) dst[jn] = acc[im][jn] + bias[n0 + tx * 8 + jn];
    }
}

// ---- GEMM2: n1 3x3 conv, implicit im2col, split-K=8.  M=3136 K=18432 N=128 ----
__global__ __launch_bounds__(256, 3) void k_gemm_n1() {
    __shared__ float As[32 * 65];
    __shared__ float Bs[32 * 128];
    const int tid = threadIdx.x;
    const int m0 = blockIdx.x * 64, s = blockIdx.z;
    const int kl = tid & 31, mr = tid >> 5;
    const int ty = tid >> 4, tx = tid & 15;
    int mb[8], my[8], mx[8];
#pragma unroll
    for (int l = 0; l < 8; l++) {
        int m = m0 + mr + l * 8;
        int b = m / 196, p = m - b * 196, yy = p / 14;
        mb[l] = b * 196; my[l] = yy; mx[l] = p - yy * 14;
    }
    float acc[4][8];
#pragma unroll
    for (int a = 0; a < 4; a++)
#pragma unroll
        for (int q = 0; q < 8; q++) acc[a][q] = 0.f;
    for (int kt = s * 72; kt < s * 72 + 72; kt++) {
        int u = kt >> 6;
        int dy = u / 3 - 1, dx = u - (u / 3) * 3 - 1;
        int cb = ((kt & 63) << 5) + kl;
#pragma unroll
        for (int l = 0; l < 8; l++) {
            int ys = my[l] + dy, xs = mx[l] + dx;
            float v = 0.f;
            if ((unsigned)ys < 14u && (unsigned)xs < 14u)
                v = __ldg(&g_raw[(size_t)(mb[l] + ys * 14 + xs) * 2048 + cb]);
            As[kl * 65 + mr + l * 8] = v;
        }
        const float* bsrc = g_w1t + (size_t)kt * 4096;
#pragma unroll
        for (int l = 0; l < 16; l++) Bs[tid + l * 256] = bsrc[tid + l * 256];
        __syncthreads();
        mac_tile(As, Bs, acc, ty, tx);
        __syncthreads();
    }
#pragma unroll
    for (int im = 0; im < 4; im++) {
        float* dst = g_y1p + (size_t)(s * 3136 + m0 + ty * 4 + im) * 128 + tx * 8;
#pragma unroll
        for (int jn = 0; jn < 8; jn++) dst[jn] = acc[im][jn];
    }
}

__global__ void k_reduce_y1(const float* __restrict__ db) {
    int gid = blockIdx.x * 256 + threadIdx.x; // 401408
    float v = db[gid & 127];
#pragma unroll
    for (int s = 0; s < 8; s++) v += g_y1p[(size_t)s * 401408 + gid];
    g_y1[gid] = fmaxf(v, 0.f);
}

// ---- small strided 3x3 convs, NHWC ----
template <int IN, int OUTW>
__device__ __forceinline__ void conv_s2_body(const float* __restrict__ yin,
                                             const float* __restrict__ wt,
                                             const float* __restrict__ bias,
                                             float* __restrict__ yout) {
    const int b = blockIdx.x, oy = blockIdx.y, o = threadIdx.x; // 128 threads
    __shared__ float s[3][IN][128];
#pragma unroll
    for (int ky = 0; ky < 3; ky++) {
        int iy = oy * 2 - 1 + ky;
        for (int t = 0; t < IN; t++)
            s[ky][t][o] = (iy >= 0 && iy < IN) ? yin[((size_t)(b * IN + iy) * IN + t) * 128 + o] : 0.f;
    }
    __syncthreads();
    float acc[OUTW];
#pragma unroll
    for (int ox = 0; ox < OUTW; ox++) acc[ox] = bias[o];
#pragma unroll
    for (int ky = 0; ky < 3; ky++)
#pragma unroll
        for (int kx = 0; kx < 3; kx++) {
            const float* wp = wt + (size_t)((ky * 3 + kx) * 128) * 128 + o;
            for (int c = 0; c < 128; c++) {
                float wv = wp[(size_t)c * 128];
#pragma unroll
                for (int ox = 0; ox < OUTW; ox++) {
                    int xs = ox * 2 + kx - 1;
                    if (xs >= 0 && xs < IN) acc[ox] += s[ky][xs][c] * wv;
                }
            }
        }
#pragma unroll
    for (int ox = 0; ox < OUTW; ox++)
        yout[((size_t)(b * OUTW + oy) * OUTW + ox) * 128 + o] = fmaxf(acc[ox], 0.f);
}
__global__ void k_conv_n2(const float* __restrict__ b) { conv_s2_body<14, 7>(g_y1, g_w2t, b, g_y2); }
__global__ void k_conv_n3(const float* __restrict__ b) { conv_s2_body<7, 4>(g_y2, g_w3t, b, g_y3); }

// ---- RPN scores (1x1 convs) ----
__global__ void k_scores(const float* __restrict__ t1w, const float* __restrict__ t1b,
                         const float* __restrict__ t2w, const float* __restrict__ t2b,
                         const float* __restrict__ t3w, const float* __restrict__ t3b) {
    int gid = blockIdx.x * 256 + threadIdx.x;
    if (gid >= 16 * NA) return;
    int b = gid / NA, r = gid - b * NA;
    const float *f, *w; float bv;
    if (r < 1176) {
        int a = r / 196, p = r - a * 196;
        f = g_y1 + (size_t)(b * 196 + p) * 128; w = t1w + a * 128; bv = t1b[a];
    } else if (r < 1470) {
        int rr = r - 1176, a = rr / 49, p = rr - a * 49;
        f = g_y2 + (size_t)(b * 49 + p) * 128; w = t2w + a * 128; bv = t2b[a];
    } else {
        int rr = r - 1470, a = rr >> 4, p = rr & 15;
        f = g_y3 + (size_t)(b * 16 + p) * 128; w = t3w + a * 128; bv = t3b[a];
    }
    float acc = bv;
#pragma unroll 4
    for (int c = 0; c < 128; c++) acc += f[c] * w[c];
    g_rpn[gid] = acc;
}

// ---- NMS: one block/batch, deterministic first-max argmax ----
__global__ void k_nms(const int* __restrict__ an) {
    const int b = blockIdx.x, tid = threadIdx.x;
    __shared__ float sc[NA];
    __shared__ int vld[NA];
    __shared__ float rv[256];
    __shared__ int ri[256];
    __shared__ int pick;
    for (int i = tid; i < NA; i += 256) { sc[i] = g_rpn[b * NA + i]; vld[i] = 1; }
    __syncthreads();
    for (int it = 0; it < 4; it++) {
        float v = -3.0e38f; int idx = NA;
        for (int i = tid; i < NA; i += 256)
            if (vld[i]) { float sv = sc[i]; if (sv > v) { v = sv; idx = i; } }
        rv[tid] = v; ri[tid] = idx;
        __syncthreads();
        for (int st = 128; st; st >>= 1) {
            if (tid < st) {
                float v2 = rv[tid + st]; int i2 = ri[tid + st];
                if (v2 > rv[tid] || (v2 == rv[tid] && i2 < ri[tid])) { rv[tid] = v2; ri[tid] = i2; }
            }
            __syncthreads();
        }
        if (tid == 0) { pick = ri[0]; g_top[b * 4 + it] = ri[0]; }
        __syncthreads();
        int pi = pick;
        float py0 = (float)an[pi * 4], px0 = (float)an[pi * 4 + 1];
        float py1 = (float)an[pi * 4 + 2], px1 = (float)an[pi * 4 + 3];
        float pa = (py1 - py0) * (px1 - px0);
        for (int i = tid; i < NA; i += 256) {
            float y0 = (float)an[i * 4], x0 = (float)an[i * 4 + 1];
            float y1 = (float)an[i * 4 + 2], x1 = (float)an[i * 4 + 3];
            float ih = fminf(y1, py1) - fmaxf(y0, py0);
            float iw = fminf(x1, px1) - fmaxf(x0, px0);
            float inter = (ih < 0.f || iw < 0.f) ? 0.f : ih * iw;
            float iou = inter / ((y1 - y0) * (x1 - x0) + pa - inter);
            if (iou >= 0.25f) vld[i] = 0;
        }
        __syncthreads();
    }
}

// ---- mean bilinear patch matrix: abar[64][3072] ----
__global__ void k_abar(const float* __restrict__ x, const int* __restrict__ an) {
    int gid = blockIdx.x * 256 + threadIdx.x; // 196608
    int p = gid / 3072, k = gid - p * 3072;
    int c = k >> 10, ky = (k >> 5) & 31, kx = k & 31;
    int b = p >> 2;
    int ai = g_top[p];
    int y0 = an[ai * 4], x0 = an[ai * 4 + 1], y1 = an[ai * 4 + 2], x1 = an[ai * 4 + 3];
    float hm1 = (float)(y1 - y0 - 1), wm1 = (float)(x1 - x0 - 1);
    int ix0[7], ix1[7]; float wx[7];
#pragma unroll
    for (int tj = 0; tj < 7; tj++) {
        float sx = __fdiv_rn((float)(tj * 32 + kx) * wm1, 223.f);
        float fx = floorf(sx);
        wx[tj] = sx - fx;
        int i0 = x0 + (int)fx;
        ix0[tj] = i0 - 224;
        ix1[tj] = min(i0 + 1, x1 - 1) - 224;
    }
    const float* xb = x + (size_t)(b * 3 + c) * 200704;
    float acc = 0.f;
#pragma unroll
    for (int ti = 0; ti < 7; ti++) {
        float sy = __fdiv_rn((float)(ti * 32 + ky) * hm1, 223.f);
        float fy = floorf(sy);
        float wy = sy - fy;
        int ry0 = y0 + (int)fy - 224;
        int ry1 = min(y0 + (int)fy + 1, y1 - 1) - 224;
        bool v0 = (unsigned)ry0 < 448u, v1 = (unsigned)ry1 < 448u;
#pragma unroll
        for (int tj = 0; tj < 7; tj++) {
            int cx0 = ix0[tj], cx1 = ix1[tj];
            bool u0 = (unsigned)cx0 < 448u, u1 = (unsigned)cx1 < 448u;
            float v00 = (v0 && u0) ? xb[ry0 * 448 + cx0] : 0.f;
            float v01 = (v0 && u1) ? xb[ry0 * 448 + cx1] : 0.f;
            float v10 = (v1 && u0) ? xb[ry1 * 448 + cx0] : 0.f;
            float v11 = (v1 && u1) ? xb[ry1 * 448 + cx1] : 0.f;
            float w = wx[tj];
            float top = v00 * (1.f - w) + v01 * w;
            float bot = v10 * (1.f - w) + v11 * w;
            acc += top * (1.f - wy) + bot * wy;
        }
    }
    g_abar[gid] = acc * (1.f / 49.f);
}

// ---- GEMM3: part feats = abar @ bbwt, split-K=8.  M=64 K=3072 N=2048 ----
__global__ __launch_bounds__(256, 3) void k_gemm_part() {
    __shared__ float As[32 * 65];
    __shared__ float Bs[32 * 128];
    const int tid = threadIdx.x;
    const int n0 = blockIdx.y * 128, s = blockIdx.z;
    const int kl = tid & 31, mr = tid >> 5;
    const int ty = tid >> 4, tx = tid & 15;
    float acc[4][8];
#pragma unroll
    for (int a = 0; a < 4; a++)
#pragma unroll
        for (int q = 0; q < 8; q++) acc[a][q] = 0.f;
    for (int kt = s * 12; kt < s * 12 + 12; kt++) {
#pragma unroll
        for (int l = 0; l < 8; l++)
            As[kl * 65 + mr + l * 8] = g_abar[(size_t)(mr + l * 8) * 3072 + kt * 32 + kl];
        const float* bsrc = g_bbwt + (size_t)kt * 65536 + n0;
#pragma unroll
        for (int l = 0; l < 16; l++) {
            int e = tid + l * 256;
            Bs[e] = bsrc[(e >> 7) * 2048 + (e & 127)];
        }
        __syncthreads();
        mac_tile(As, Bs, acc, ty, tx);
        __syncthreads();
    }
#pragma unroll
    for (int im = 0; im < 4; im++) {
        float* dst = g_pfp + (size_t)(s * 64 + ty * 4 + im) * 2048 + n0 + tx * 8;
#pragma unroll
        for (int jn = 0; jn < 8; jn++) dst[jn] = acc[im][jn];
    }
}

__global__ void k_reduce_part(const float* __restrict__ bb) {
    int gid = blockIdx.x * 256 + threadIdx.x; // 131072
    float v = bb[gid & 2047];
#pragma unroll
    for (int s = 0; s < 8; s++) v += g_pfp[(size_t)s * 131072 + gid];
    g_pf[gid] = v;
}

__global__ void k_rawfeat() {
    int gid = blockIdx.x * 256 + threadIdx.x; // 32768
    int b = gid >> 11, o = gid & 2047;
    float v = 0.f;
    for (int p = 0; p < 196; p++) v += g_raw[(size_t)(b * 196 + p) * 2048 + o];
    g_rf[gid] = v * (1.f / 196.f);
}

// ---- classifier: warp per (b, cls) ----
__global__ void k_classifier(const float* __restrict__ cw, const float* __restrict__ cb,
                             float* __restrict__ out) {
    int w = blockIdx.x * 8 + (threadIdx.x >> 5); // 3200 warps
    int lane = threadIdx.x & 31;
    int b = w / 200, cls = w - b * 200;
    const float* wr = cw + (size_t)cls * 10240;
    const float* pf = g_pf + (size_t)b * 4 * 2048;
    const float* rf = g_rf + (size_t)b * 2048;
    float acc = 0.f;
    for (int j = lane; j < 8192; j += 32) acc += pf[j] * wr[j];
    for (int j = lane; j < 2048; j += 32) acc += rf[j] * wr[8192 + j];
#pragma unroll
    for (int st = 16; st; st >>= 1) acc += __shfl_xor_sync(0xffffffffu, acc, st);
    if (lane == 0) out[w] = acc + cb[cls];
}

extern "C" void kernel_launch(void* const* d_in, const int* in_sizes, int n_in,
                              void* d_out, int out_size) {
    const float* x     = (const float*)d_in[0];
    const float* bb_w  = (const float*)d_in[1];
    const float* bb_b  = (const float*)d_in[2];
    const float* n1_dw = (const float*)d_in[3];
    const float* n1_db = (const float*)d_in[4];
    const float* n1_tw = (const float*)d_in[5];
    const float* n1_tb = (const float*)d_in[6];
    const float* n2_dw = (const float*)d_in[7];
    const float* n2_db = (const float*)d_in[8];
    const float* n2_tw = (const float*)d_in[9];
    const float* n2_tb = (const float*)d_in[10];
    const float* n3_dw = (const float*)d_in[11];
    const float* n3_db = (const float*)d_in[12];
    const float* n3_tw = (const float*)d_in[13];
    const float* n3_tb = (const float*)d_in[14];
    const float* cn_w  = (const float*)d_in[15];
    const float* cn_b  = (const float*)d_in[16];
    const int*   anch  = (const int*)d_in[17];
    float* out = (float*)d_out;

    k_transpose_bbw<<<dim3(96, 64), dim3(32, 8)>>>(bb_w);
    k_repack_w1<<<9216, 256>>>(n1_dw);
    k_repack_w2<<<576, 256>>>(n2_dw);
    k_repack_w3<<<576, 256>>>(n3_dw);
    k_gemm_raw<<<dim3(49, 16), 256>>>(x, bb_b);
    k_gemm_n1<<<dim3(49, 1, 8), 256>>>();
    k_reduce_y1<<<1568, 256>>>(n1_db);
    k_conv_n2<<<dim3(16, 7), 128>>>(n2_db);
    k_conv_n3<<<dim3(16, 4), 128>>>(n3_db);
    k_scores<<<101, 256>>>(n1_tw, n1_tb, n2_tw, n2_tb, n3_tw, n3_tb);
    k_nms<<<16, 256>>>(anch);
    k_abar<<<768, 256>>>(x, anch);
    k_gemm_part<<<dim3(1, 16, 8), 256>>>();
    k_reduce_part<<<512, 256>>>(bb_b);
    k_rawfeat<<<128, 256>>>();
    k_classifier<<<400, 256>>>(cn_w, cn_b, out);
}

// round 12
// speedup vs baseline: 1.1461x; 1.1461x over previous
#include <cuda_runtime.h>
#include <cuda_bf16.h>
#include <cstdint>
#include <stdint.h>
#include <math.h>

#define ANCH_N 1614

// ================= static device scratch =================
__device__ float g_bbwt[3072 * 2048];
__device__ float g_raw [3136 * 2048];
__device__ __nv_bfloat16 g_a1[3200 * 9216];
__device__ __nv_bfloat16 g_b1[2048 * 9216];
__device__ __nv_bfloat16 g_rawhi[3136 * 2048];
__device__ __nv_bfloat16 g_rawlo[3136 * 2048];
__device__ __nv_bfloat16 g_w1b[128 * 55296];
__device__ float g_y1p [6 * 3136 * 128];
__device__ float g_y1  [3136 * 128];
__device__ float g_w2t [1152 * 128];
__device__ float g_w3t [1152 * 128];
__device__ float g_y2  [16 * 49 * 128];
__device__ float g_y3  [16 * 16 * 128];
__device__ float g_rpn [16 * ANCH_N];
__device__ int   g_top [64];
__device__ float g_abar[64 * 3072];
__device__ float g_pfp [8 * 64 * 2048];
__device__ float g_pf  [64 * 2048];
__device__ float g_rf  [16 * 2048];

// ================= warp-MMA helpers (base-target instructions only) =================
__device__ __forceinline__ uint32_t smem_addr_u32(const void* p) {
    uint32_t a;
    asm("{ .reg .u64 t; cvta.to.shared.u64 t, %1; cvt.u32.u64 %0, t; }" : "=r"(a) : "l"(p));
    return a;
}
#define LDMX4(r0, r1, r2, r3, a) \
    asm volatile("ldmatrix.sync.aligned.m8n8.x4.shared.b16 {%0,%1,%2,%3}, [%4];" \
                 : "=r"(r0), "=r"(r1), "=r"(r2), "=r"(r3) : "r"(a))
#define MMA16816(d, a0, a1, a2, a3, b0, b1) \
    asm volatile("mma.sync.aligned.m16n8k16.row.col.f32.bf16.bf16.f32 " \
                 "{%0,%1,%2,%3}, {%4,%5,%6,%7}, {%8,%9}, {%0,%1,%2,%3};" \
                 : "+f"((d)[0]), "+f"((d)[1]), "+f"((d)[2]), "+f"((d)[3]) \
                 : "r"(a0), "r"(a1), "r"(a2), "r"(a3), "r"(b0), "r"(b1))

__device__ __forceinline__ void split_bf16(float a, __nv_bfloat16& hi, __nv_bfloat16& lo) {
    hi = __float2bfloat16_rn(a);
    lo = __float2bfloat16_rn(a - __bfloat162float(hi));
}

// ================= operand builders =================
__global__ void k_build_a1(const float* __restrict__ x) {
    int gid = blockIdx.x * 256 + threadIdx.x;            // 3200*9216
    int m = gid / 9216, kk = gid - m * 9216;
    int s = kk / 3072, k = kk - s * 3072;
    float a = 0.f;
    if (m < 3136) {
        int c = k >> 10, r = (k >> 5) & 31, q = k & 31;
        int b = m / 196, p = m - b * 196, i = p / 14, j = p - i * 14;
        a = x[((size_t)(b * 3 + c) * 448 + i * 32 + r) * 448 + j * 32 + q];
    }
    __nv_bfloat16 hi, lo; split_bf16(a, hi, lo);
    g_a1[gid] = (s == 1) ? lo : hi;
}
__global__ void k_build_b1(const float* __restrict__ w) {
    int gid = blockIdx.x * 256 + threadIdx.x;            // 2048*9216
    int n = gid / 9216, kk = gid - n * 9216;
    int s = kk / 3072, k = kk - s * 3072;
    __nv_bfloat16 hi, lo; split_bf16(w[(size_t)n * 3072 + k], hi, lo);
    g_b1[gid] = (s == 2) ? lo : hi;
}
__global__ void k_build_w1b(const float* __restrict__ w) {
    int gid = blockIdx.x * 256 + threadIdx.x;            // 128*55296
    int o = gid / 55296, kk = gid - o * 55296;
    int s = kk / 18432, r2 = kk - s * 18432, u = r2 >> 11, c = r2 & 2047;
    __nv_bfloat16 hi, lo; split_bf16(w[(size_t)(o * 2048 + c) * 9 + u], hi, lo);
    g_w1b[gid] = (s == 2) ? lo : hi;
}

// ================= GEMM1: raw = A1' @ B1'^T + bias (HMMA) =================
// grid (25, 16), 256 thr. Tile 128x128, BK=32, warp tile 32x64.
__global__ __launch_bounds__(256) void k_mm1(const float* __restrict__ bias) {
    __shared__ __nv_bfloat16 As[128][40];
    __shared__ __nv_bfloat16 Bs[128][40];
    const int tid = threadIdx.x, wid = tid >> 5, lane = tid & 31;
    const int m0 = blockIdx.x * 128, n0 = blockIdx.y * 128;
    const int wm = wid & 3, wn = wid >> 2;         // 4 x 2 warps
    const int lr = tid >> 1, lq = tid & 1;         // loader row / half
    const int quad = lane >> 3, qr = lane & 7;     // ldmatrix addressing
    const int g = lane >> 2, tg = lane & 3;

    const uint4* gA = (const uint4*)(g_a1 + (size_t)(m0 + lr) * 9216);
    const uint4* gB = (const uint4*)(g_b1 + (size_t)(n0 + lr) * 9216);

    float acc[2][8][4];
#pragma unroll
    for (int i = 0; i < 2; i++)
#pragma unroll
        for (int j = 0; j < 8; j++)
#pragma unroll
            for (int v = 0; v < 4; v++) acc[i][j][v] = 0.f;

    // precompute ldmatrix smem addresses (k0-relative)
    uint32_t aAddr[2], bAddr[4];
#pragma unroll
    for (int mt = 0; mt < 2; mt++)
        aAddr[mt] = smem_addr_u32(&As[wm * 32 + mt * 16 + (quad & 1) * 8 + qr][(quad >> 1) * 8]);
#pragma unroll
    for (int bt = 0; bt < 4; bt++)
        bAddr[bt] = smem_addr_u32(&Bs[wn * 64 + bt * 16 + (quad >> 1) * 8 + qr][(quad & 1) * 8]);

    uint4 ra0 = gA[lq * 2], ra1 = gA[lq * 2 + 1];
    uint4 rb0 = gB[lq * 2], rb1 = gB[lq * 2 + 1];

    for (int t = 0; t < 288; t++) {
        *(uint4*)&As[lr][lq * 16 + 0] = ra0;
        *(uint4*)&As[lr][lq * 16 + 8] = ra1;
        *(uint4*)&Bs[lr][lq * 16 + 0] = rb0;
        *(uint4*)&Bs[lr][lq * 16 + 8] = rb1;
        __syncthreads();
        if (t + 1 < 288) {
            int o = (t + 1) * 4 + lq * 2;
            ra0 = gA[o]; ra1 = gA[o + 1];
            rb0 = gB[o]; rb1 = gB[o + 1];
        }
#pragma unroll
        for (int ks = 0; ks < 2; ks++) {
            uint32_t af[2][4], bf[4][4];
#pragma unroll
            for (int mt = 0; mt < 2; mt++)
                LDMX4(af[mt][0], af[mt][1], af[mt][2], af[mt][3], aAddr[mt] + ks * 32);
#pragma unroll
            for (int bt = 0; bt < 4; bt++)
                LDMX4(bf[bt][0], bf[bt][1], bf[bt][2], bf[bt][3], bAddr[bt] + ks * 32);
#pragma unroll
            for (int mt = 0; mt < 2; mt++)
#pragma unroll
                for (int nt = 0; nt < 8; nt++) {
                    uint32_t b0 = bf[nt >> 1][(nt & 1) * 2];
                    uint32_t b1 = bf[nt >> 1][(nt & 1) * 2 + 1];
                    MMA16816(acc[mt][nt], af[mt][0], af[mt][1], af[mt][2], af[mt][3], b0, b1);
                }
        }
        __syncthreads();
    }

    // epilogue: bias add, write raw (f32) + fused hi/lo split
#pragma unroll
    for (int mt = 0; mt < 2; mt++) {
#pragma unroll
        for (int nt = 0; nt < 8; nt++) {
            int n = n0 + wn * 64 + nt * 8 + tg * 2;
            float bv0 = bias[n], bv1 = bias[n + 1];
            int m1 = m0 + wm * 32 + mt * 16 + g;
#pragma unroll
            for (int h = 0; h < 2; h++) {
                int mm = m1 + h * 8;
                if (mm < 3136) {
                    float v0 = acc[mt][nt][h * 2 + 0] + bv0;
                    float v1 = acc[mt][nt][h * 2 + 1] + bv1;
                    size_t off = (size_t)mm * 2048 + n;
                    g_raw[off] = v0; g_raw[off + 1] = v1;
                    __nv_bfloat16 h0, l0, h1, l1;
                    split_bf16(v0, h0, l0); split_bf16(v1, h1, l1);
                    g_rawhi[off] = h0; g_rawhi[off + 1] = h1;
                    g_rawlo[off] = l0; g_rawlo[off + 1] = l1;
                }
            }
        }
    }
}

// ================= GEMM2: n1 implicit-im2col, split-K=6 (HMMA) =================
// grid (25, 1, 6), 256 thr. M tile 128, N = 128, BK=32, 288 iters/split.
__global__ __launch_bounds__(256) void k_mm2() {
    __shared__ __nv_bfloat16 As[128][40];
    __shared__ __nv_bfloat16 Bs[128][40];
    const int tid = threadIdx.x, wid = tid >> 5, lane = tid & 31;
    const int m0 = blockIdx.x * 128, sK = blockIdx.z;
    const int wm = wid & 3, wn = wid >> 2;
    const int lr = tid >> 1, lq = tid & 1;
    const int quad = lane >> 3, qr = lane & 7;
    const int g = lane >> 2, tg = lane & 3;

    // decode gather row
    const int m = m0 + lr;
    int bq = 0, yy = 0, xx = 0;
    const bool mrow_ok = (m < 3136);
    if (mrow_ok) { bq = m / 196; int pp = m - bq * 196; yy = pp / 14; xx = pp - yy * 14; }
    const uint4* gB = (const uint4*)(g_w1b + (size_t)lr * 55296);

    float acc[2][8][4];
#pragma unroll
    for (int i = 0; i < 2; i++)
#pragma unroll
        for (int j = 0; j < 8; j++)
#pragma unroll
            for (int v = 0; v < 4; v++) acc[i][j][v] = 0.f;

    uint32_t aAddr[2], bAddr[4];
#pragma unroll
    for (int mt = 0; mt < 2; mt++)
        aAddr[mt] = smem_addr_u32(&As[wm * 32 + mt * 16 + (quad & 1) * 8 + qr][(quad >> 1) * 8]);
#pragma unroll
    for (int bt = 0; bt < 4; bt++)
        bAddr[bt] = smem_addr_u32(&Bs[wn * 64 + bt * 16 + (quad >> 1) * 8 + qr][(quad & 1) * 8]);

    const int kt0 = sK * 288;
    uint4 ra0, ra1, rb0, rb1;
    // prologue load for t=0
    {
        int kt = kt0;
        int sp = kt / 576, r2 = kt - sp * 576, u = r2 >> 6, c0 = (r2 & 63) << 5;
        int ys = yy + u / 3 - 1, xs = xx + (u % 3) - 1;
        bool ok = mrow_ok && ((unsigned)ys < 14u) && ((unsigned)xs < 14u);
        const __nv_bfloat16* rsrc = (sp == 1) ? g_rawlo : g_rawhi;
        const uint4* pa = (const uint4*)(rsrc + (size_t)(bq * 196 + ys * 14 + xs) * 2048 + c0);
        ra0 = ok ? pa[lq * 2] : make_uint4(0u, 0u, 0u, 0u);
        ra1 = ok ? pa[lq * 2 + 1] : make_uint4(0u, 0u, 0u, 0u);
        rb0 = gB[kt * 4 + lq * 2]; rb1 = gB[kt * 4 + lq * 2 + 1];
    }

    for (int t = 0; t < 288; t++) {
        *(uint4*)&As[lr][lq * 16 + 0] = ra0;
        *(uint4*)&As[lr][lq * 16 + 8] = ra1;
        *(uint4*)&Bs[lr][lq * 16 + 0] = rb0;
        *(uint4*)&Bs[lr][lq * 16 + 8] = rb1;
        __syncthreads();
        if (t + 1 < 288) {
            int kt = kt0 + t + 1;
            int sp = kt / 576, r2 = kt - sp * 576, u = r2 >> 6, c0 = (r2 & 63) << 5;
            int ys = yy + u / 3 - 1, xs = xx + (u % 3) - 1;
            bool ok = mrow_ok && ((unsigned)ys < 14u) && ((unsigned)xs < 14u);
            const __nv_bfloat16* rsrc = (sp == 1) ? g_rawlo : g_rawhi;
            const uint4* pa = (const uint4*)(rsrc + (size_t)(bq * 196 + ys * 14 + xs) * 2048 + c0);
            ra0 = ok ? pa[lq * 2] : make_uint4(0u, 0u, 0u, 0u);
            ra1 = ok ? pa[lq * 2 + 1] : make_uint4(0u, 0u, 0u, 0u);
            rb0 = gB[kt * 4 + lq * 2]; rb1 = gB[kt * 4 + lq * 2 + 1];
        }
#pragma unroll
        for (int ks = 0; ks < 2; ks++) {
            uint32_t af[2][4], bf[4][4];
#pragma unroll
            for (int mt = 0; mt < 2; mt++)
                LDMX4(af[mt][0], af[mt][1], af[mt][2], af[mt][3], aAddr[mt] + ks * 32);
#pragma unroll
            for (int bt = 0; bt < 4; bt++)
                LDMX4(bf[bt][0], bf[bt][1], bf[bt][2], bf[bt][3], bAddr[bt] + ks * 32);
#pragma unroll
            for (int mt = 0; mt < 2; mt++)
#pragma unroll
                for (int nt = 0; nt < 8; nt++) {
                    uint32_t b0 = bf[nt >> 1][(nt & 1) * 2];
                    uint32_t b1 = bf[nt >> 1][(nt & 1) * 2 + 1];
                    MMA16816(acc[mt][nt], af[mt][0], af[mt][1], af[mt][2], af[mt][3], b0, b1);
                }
        }
        __syncthreads();
    }

#pragma unroll
    for (int mt = 0; mt < 2; mt++) {
#pragma unroll
        for (int nt = 0; nt < 8; nt++) {
            int n = wn * 64 + nt * 8 + tg * 2;
            int m1 = m0 + wm * 32 + mt * 16 + g;
#pragma unroll
            for (int h = 0; h < 2; h++) {
                int mm = m1 + h * 8;
                if (mm < 3136) {
                    float* dst = g_y1p + ((size_t)sK * 3136 + mm) * 128 + n;
                    dst[0] = acc[mt][nt][h * 2 + 0];
                    dst[1] = acc[mt][nt][h * 2 + 1];
                }
            }
        }
    }
}

__global__ void k_reduce_y1(const float* __restrict__ db) {
    int gid = blockIdx.x * 256 + threadIdx.x; // 401408
    float v = db[gid & 127];
#pragma unroll
    for (int s = 0; s < 6; s++) v += g_y1p[(size_t)s * 401408 + gid];
    g_y1[gid] = fmaxf(v, 0.f);
}

// ================= tail (R7-passing versions) =================
__global__ void k_transpose_bbw(const float* __restrict__ src) {
    __shared__ float tile[32][33];
    int c0 = blockIdx.x * 32, r0 = blockIdx.y * 32;
    int tx = threadIdx.x, ty = threadIdx.y;
    for (int i = ty; i < 32; i += 8)
        tile[i][tx] = src[(size_t)(r0 + i) * 3072 + c0 + tx];
    __syncthreads();
    for (int i = ty; i < 32; i += 8)
        g_bbwt[(size_t)(c0 + i) * 2048 + r0 + tx] = tile[tx][i];
}
__global__ void k_repack_w2(const float* __restrict__ src) {
    int gid = blockIdx.x * 256 + threadIdx.x;
    int k = gid >> 7, o = gid & 127, u = k >> 7, c = k & 127;
    g_w2t[gid] = src[(o * 128 + c) * 9 + u];
}
__global__ void k_repack_w3(const float* __restrict__ src) {
    int gid = blockIdx.x * 256 + threadIdx.x;
    int k = gid >> 7, o = gid & 127, u = k >> 7, c = k & 127;
    g_w3t[gid] = src[(o * 128 + c) * 9 + u];
}
template <int IN, int OUTW>
__device__ __forceinline__ void conv_s2_body(const float* __restrict__ yin,
                                             const float* __restrict__ wt,
                                             const float* __restrict__ bias,
                                             float* __restrict__ yout) {
    const int b = blockIdx.x, oy = blockIdx.y, o = threadIdx.x;
    __shared__ float s[3][IN][128];
#pragma unroll
    for (int ky = 0; ky < 3; ky++) {
        int iy = oy * 2 - 1 + ky;
        for (int t = 0; t < IN; t++)
            s[ky][t][o] = (iy >= 0 && iy < IN) ? yin[((size_t)(b * IN + iy) * IN + t) * 128 + o] : 0.f;
    }
    __syncthreads();
    float acc[OUTW];
#pragma unroll
    for (int ox = 0; ox < OUTW; ox++) acc[ox] = bias[o];
#pragma unroll
    for (int ky = 0; ky < 3; ky++)
#pragma unroll
        for (int kx = 0; kx < 3; kx++) {
            const float* wp = wt + (size_t)((ky * 3 + kx) * 128) * 128 + o;
            for (int c = 0; c < 128; c++) {
                float wv = wp[(size_t)c * 128];
#pragma unroll
                for (int ox = 0; ox < OUTW; ox++) {
                    int xs = ox * 2 + kx - 1;
                    if (xs >= 0 && xs < IN) acc[ox] += s[ky][xs][c] * wv;
                }
            }
        }
#pragma unroll
    for (int ox = 0; ox < OUTW; ox++)
        yout[((size_t)(b * OUTW + oy) * OUTW + ox) * 128 + o] = fmaxf(acc[ox], 0.f);
}
__global__ void k_conv_n2(const float* __restrict__ b) { conv_s2_body<14, 7>(g_y1, g_w2t, b, g_y2); }
__global__ void k_conv_n3(const float* __restrict__ b) { conv_s2_body<7, 4>(g_y2, g_w3t, b, g_y3); }

__global__ void k_scores(const float* __restrict__ t1w, const float* __restrict__ t1b,
                         const float* __restrict__ t2w, const float* __restrict__ t2b,
                         const float* __restrict__ t3w, const float* __restrict__ t3b) {
    int gid = blockIdx.x * 256 + threadIdx.x;
    if (gid >= 16 * ANCH_N) return;
    int b = gid / ANCH_N, r = gid - b * ANCH_N;
    const float *f, *w; float bv;
    if (r < 1176) {
        int a = r / 196, p = r - a * 196;
        f = g_y1 + (size_t)(b * 196 + p) * 128; w = t1w + a * 128; bv = t1b[a];
    } else if (r < 1470) {
        int rr = r - 1176, a = rr / 49, p = rr - a * 49;
        f = g_y2 + (size_t)(b * 49 + p) * 128; w = t2w + a * 128; bv = t2b[a];
    } else {
        int rr = r - 1470, a = rr >> 4, p = rr & 15;
        f = g_y3 + (size_t)(b * 16 + p) * 128; w = t3w + a * 128; bv = t3b[a];
    }
    float acc = bv;
#pragma unroll 4
    for (int c = 0; c < 128; c++) acc += f[c] * w[c];
    g_rpn[gid] = acc;
}

__global__ void k_nms(const int* __restrict__ an) {
    const int b = blockIdx.x, tid = threadIdx.x;
    __shared__ float sc[ANCH_N];
    __shared__ int vld[ANCH_N];
    __shared__ float rv[256];
    __shared__ int ri[256];
    __shared__ int pick;
    for (int i = tid; i < ANCH_N; i += 256) { sc[i] = g_rpn[b * ANCH_N + i]; vld[i] = 1; }
    __syncthreads();
    for (int it = 0; it < 4; it++) {
        float v = -3.0e38f; int idx = ANCH_N;
        for (int i = tid; i < ANCH_N; i += 256)
            if (vld[i]) { float sv = sc[i]; if (sv > v) { v = sv; idx = i; } }
        rv[tid] = v; ri[tid] = idx;
        __syncthreads();
        for (int st = 128; st; st >>= 1) {
            if (tid < st) {
                float v2 = rv[tid + st]; int i2 = ri[tid + st];
                if (v2 > rv[tid] || (v2 == rv[tid] && i2 < ri[tid])) { rv[tid] = v2; ri[tid] = i2; }
            }
            __syncthreads();
        }
        if (tid == 0) { pick = ri[0]; g_top[b * 4 + it] = ri[0]; }
        __syncthreads();
        int pi = pick;
        float py0 = (float)an[pi * 4], px0 = (float)an[pi * 4 + 1];
        float py1 = (float)an[pi * 4 + 2], px1 = (float)an[pi * 4 + 3];
        float pa = (py1 - py0) * (px1 - px0);
        for (int i = tid; i < ANCH_N; i += 256) {
            float y0 = (float)an[i * 4], x0 = (float)an[i * 4 + 1];
            float y1 = (float)an[i * 4 + 2], x1 = (float)an[i * 4 + 3];
            float ih = fminf(y1, py1) - fmaxf(y0, py0);
            float iw = fminf(x1, px1) - fmaxf(x0, px0);
            float inter = (ih < 0.f || iw < 0.f) ? 0.f : ih * iw;
            float iou = inter / ((y1 - y0) * (x1 - x0) + pa - inter);
            if (iou >= 0.25f) vld[i] = 0;
        }
        __syncthreads();
    }
}

__global__ void k_abar(const float* __restrict__ x, const int* __restrict__ an) {
    int gid = blockIdx.x * 256 + threadIdx.x; // 196608
    int p = gid / 3072, k = gid - p * 3072;
    int c = k >> 10, ky = (k >> 5) & 31, kx = k & 31;
    int b = p >> 2;
    int ai = g_top[p];
    int y0 = an[ai * 4], x0 = an[ai * 4 + 1], y1 = an[ai * 4 + 2], x1 = an[ai * 4 + 3];
    float hm1 = (float)(y1 - y0 - 1), wm1 = (float)(x1 - x0 - 1);
    int ix0[7], ix1[7]; float wx[7];
#pragma unroll
    for (int tj = 0; tj < 7; tj++) {
        float sx = __fdiv_rn((float)(tj * 32 + kx) * wm1, 223.f);
        float fx = floorf(sx);
        wx[tj] = sx - fx;
        int i0 = x0 + (int)fx;
        ix0[tj] = i0 - 224;
        ix1[tj] = min(i0 + 1, x1 - 1) - 224;
    }
    const float* xb = x + (size_t)(b * 3 + c) * 200704;
    float acc = 0.f;
#pragma unroll
    for (int ti = 0; ti < 7; ti++) {
        float sy = __fdiv_rn((float)(ti * 32 + ky) * hm1, 223.f);
        float fy = floorf(sy);
        float wy = sy - fy;
        int ry0 = y0 + (int)fy - 224;
        int ry1 = min(y0 + (int)fy + 1, y1 - 1) - 224;
        bool v0 = (unsigned)ry0 < 448u, v1 = (unsigned)ry1 < 448u;
#pragma unroll
        for (int tj = 0; tj < 7; tj++) {
            int cx0 = ix0[tj], cx1 = ix1[tj];
            bool u0 = (unsigned)cx0 < 448u, u1 = (unsigned)cx1 < 448u;
            float v00 = (v0 && u0) ? xb[ry0 * 448 + cx0] : 0.f;
            float v01 = (v0 && u1) ? xb[ry0 * 448 + cx1] : 0.f;
            float v10 = (v1 && u0) ? xb[ry1 * 448 + cx0] : 0.f;
            float v11 = (v1 && u1) ? xb[ry1 * 448 + cx1] : 0.f;
            float w = wx[tj];
            float top = v00 * (1.f - w) + v01 * w;
            float bot = v10 * (1.f - w) + v11 * w;
            acc += top * (1.f - wy) + bot * wy;
        }
    }
    g_abar[gid] = acc * (1.f / 49.f);
}

__device__ __forceinline__ void mac_tile(const float* As, const float* Bs,
                                         float acc[4][8], int ty, int tx) {
#pragma unroll
    for (int kk = 0; kk < 32; kk++) {
        float a0 = As[kk * 65 + ty * 4 + 0];
        float a1 = As[kk * 65 + ty * 4 + 1];
        float a2 = As[kk * 65 + ty * 4 + 2];
        float a3 = As[kk * 65 + ty * 4 + 3];
        float4 b0 = *(const float4*)&Bs[kk * 128 + tx * 8];
        float4 b1 = *(const float4*)&Bs[kk * 128 + tx * 8 + 4];
        float bv[8] = {b0.x, b0.y, b0.z, b0.w, b1.x, b1.y, b1.z, b1.w};
#pragma unroll
        for (int j = 0; j < 8; j++) {
            acc[0][j] += a0 * bv[j];
            acc[1][j] += a1 * bv[j];
            acc[2][j] += a2 * bv[j];
            acc[3][j] += a3 * bv[j];
        }
    }
}
__global__ __launch_bounds__(256, 3) void k_gemm_part() {
    __shared__ float As[32 * 65];
    __shared__ float Bs[32 * 128];
    const int tid = threadIdx.x;
    const int n0 = blockIdx.y * 128, s = blockIdx.z;
    const int kl = tid & 31, mr = tid >> 5;
    const int ty = tid >> 4, tx = tid & 15;
    float acc[4][8];
#pragma unroll
    for (int a = 0; a < 4; a++)
#pragma unroll
        for (int q = 0; q < 8; q++) acc[a][q] = 0.f;
    for (int kt = s * 12; kt < s * 12 + 12; kt++) {
#pragma unroll
        for (int l = 0; l < 8; l++)
            As[kl * 65 + mr + l * 8] = g_abar[(size_t)(mr + l * 8) * 3072 + kt * 32 + kl];
        const float* bsrc = g_bbwt + (size_t)kt * 65536 + n0;
#pragma unroll
        for (int l = 0; l < 16; l++) {
            int e = tid + l * 256;
            Bs[e] = bsrc[(e >> 7) * 2048 + (e & 127)];
        }
        __syncthreads();
        mac_tile(As, Bs, acc, ty, tx);
        __syncthreads();
    }
#pragma unroll
    for (int im = 0; im < 4; im++) {
        float* dst = g_pfp + (size_t)(s * 64 + ty * 4 + im) * 2048 + n0 + tx * 8;
#pragma unroll
        for (int jn = 0; jn < 8; jn++) dst[jn] = acc[im][jn];
    }
}
__global__ void k_reduce_part(const float* __restrict__ bb) {
    int gid = blockIdx.x * 256 + threadIdx.x; // 131072
    float v = bb[gid & 2047];
#pragma unroll
    for (int s = 0; s < 8; s++) v += g_pfp[(size_t)s * 131072 + gid];
    g_pf[gid] = v;
}
__global__ void k_rawfeat() {
    int gid = blockIdx.x * 256 + threadIdx.x; // 32768
    int b = gid >> 11, o = gid & 2047;
    float v = 0.f;
    for (int p = 0; p < 196; p++) v += g_raw[(size_t)(b * 196 + p) * 2048 + o];
    g_rf[gid] = v * (1.f / 196.f);
}
__global__ void k_classifier(const float* __restrict__ cw, const float* __restrict__ cb,
                             float* __restrict__ out) {
    int w = blockIdx.x * 8 + (threadIdx.x >> 5);
    int lane = threadIdx.x & 31;
    int b = w / 200, cls = w - b * 200;
    const float* wr = cw + (size_t)cls * 10240;
    const float* pf = g_pf + (size_t)b * 4 * 2048;
    const float* rf = g_rf + (size_t)b * 2048;
    float acc = 0.f;
    for (int j = lane; j < 8192; j += 32) acc += pf[j] * wr[j];
    for (int j = lane; j < 2048; j += 32) acc += rf[j] * wr[8192 + j];
#pragma unroll
    for (int st = 16; st; st >>= 1) acc += __shfl_xor_sync(0xffffffffu, acc, st);
    if (lane == 0) out[w] = acc + cb[cls];
}

// ================= launch =================
extern "C" void kernel_launch(void* const* d_in, const int* in_sizes, int n_in,
                              void* d_out, int out_size) {
    const float* x     = (const float*)d_in[0];
    const float* bb_w  = (const float*)d_in[1];
    const float* bb_b  = (const float*)d_in[2];
    const float* n1_dw = (const float*)d_in[3];
    const float* n1_db = (const float*)d_in[4];
    const float* n1_tw = (const float*)d_in[5];
    const float* n1_tb = (const float*)d_in[6];
    const float* n2_dw = (const float*)d_in[7];
    const float* n2_db = (const float*)d_in[8];
    const float* n2_tw = (const float*)d_in[9];
    const float* n2_tb = (const float*)d_in[10];
    const float* n3_dw = (const float*)d_in[11];
    const float* n3_db = (const float*)d_in[12];
    const float* n3_tw = (const float*)d_in[13];
    const float* n3_tb = (const float*)d_in[14];
    const float* cn_w  = (const float*)d_in[15];
    const float* cn_b  = (const float*)d_in[16];
    const int*   anch  = (const int*)d_in[17];
    float* out = (float*)d_out;

    k_build_a1<<<115200, 256>>>(x);
    k_build_b1<<<73728, 256>>>(bb_w);
    k_build_w1b<<<27648, 256>>>(n1_dw);
    k_transpose_bbw<<<dim3(96, 64), dim3(32, 8)>>>(bb_w);
    k_repack_w2<<<576, 256>>>(n2_dw);
    k_repack_w3<<<576, 256>>>(n3_dw);
    k_mm1<<<dim3(25, 16), 256>>>(bb_b);
    k_mm2<<<dim3(25, 1, 6), 256>>>();
    k_reduce_y1<<<1568, 256>>>(n1_db);
    k_conv_n2<<<dim3(16, 7), 128>>>(n2_db);
    k_conv_n3<<<dim3(16, 4), 128>>>(n3_db);
    k_scores<<<101, 256>>>(n1_tw, n1_tb, n2_tw, n2_tb, n3_tw, n3_tb);
    k_nms<<<16, 256>>>(anch);
    k_abar<<<768, 256>>>(x, anch);
    k_gemm_part<<<dim3(1, 16, 8), 256>>>();
    k_reduce_part<<<512, 256>>>(bb_b);
    k_rawfeat<<<128, 256>>>();
    k_classifier<<<400, 256>>>(cn_w, cn_b, out);
}

// round 14
// speedup vs baseline: 1.6800x; 1.4659x over previous
#include <cuda_runtime.h>
#include <cuda_bf16.h>
#include <cstdint>
#include <stdint.h>
#include <math.h>

#define ANCH_N 1614

// ================= static device scratch =================
__device__ float g_bbwt[3072 * 2048];
__device__ float g_raw [3136 * 2048];
__device__ __nv_bfloat16 g_a1[3200 * 9216];
__device__ __nv_bfloat16 g_b1[2048 * 9216];
__device__ __nv_bfloat16 g_rawhi[3136 * 2048];
__device__ __nv_bfloat16 g_rawlo[3136 * 2048];
__device__ __nv_bfloat16 g_w1b[128 * 55296];
__device__ float g_y1p [6 * 3136 * 128];
__device__ float g_y1  [3136 * 128];
__device__ float g_w2t [1152 * 128];
__device__ float g_w3t [1152 * 128];
__device__ float g_y2  [16 * 49 * 128];
__device__ float g_y3  [16 * 16 * 128];
__device__ float g_rpn [16 * ANCH_N];
__device__ int   g_top [64];
__device__ float g_abar[64 * 3072];
__device__ float g_pfp [8 * 64 * 2048];
__device__ float g_pf  [64 * 2048];
__device__ float g_rf  [16 * 2048];

// ================= warp-MMA helpers (base-target instructions only) =================
__device__ __forceinline__ uint32_t smem_addr_u32(const void* p) {
    uint32_t a;
    asm("{ .reg .u64 t; cvta.to.shared.u64 t, %1; cvt.u32.u64 %0, t; }" : "=r"(a) : "l"(p));
    return a;
}
#define LDMX4(r0, r1, r2, r3, a) \
    asm volatile("ldmatrix.sync.aligned.m8n8.x4.shared.b16 {%0,%1,%2,%3}, [%4];" \
                 : "=r"(r0), "=r"(r1), "=r"(r2), "=r"(r3) : "r"(a))
#define MMA16816(d, a0, a1, a2, a3, b0, b1) \
    asm volatile("mma.sync.aligned.m16n8k16.row.col.f32.bf16.bf16.f32 " \
                 "{%0,%1,%2,%3}, {%4,%5,%6,%7}, {%8,%9}, {%0,%1,%2,%3};" \
                 : "+f"((d)[0]), "+f"((d)[1]), "+f"((d)[2]), "+f"((d)[3]) \
                 : "r"(a0), "r"(a1), "r"(a2), "r"(a3), "r"(b0), "r"(b1))
#define CPA16(dst, src) \
    asm volatile("cp.async.ca.shared.global [%0], [%1], 16;" :: "r"(dst), "l"(src))
#define CPA16Z(dst, src, okbytes) \
    asm volatile("cp.async.ca.shared.global [%0], [%1], 16, %2;" :: "r"(dst), "l"(src), "r"(okbytes))
#define CPCOMMIT() asm volatile("cp.async.commit_group;" ::: "memory")
#define CPWAIT2()  asm volatile("cp.async.wait_group 2;" ::: "memory")

// stage: A 128x72 bf16 (18432 B) + B 128x72 bf16 -> 36864 B; 3 stages = 110592 B
#define MM_STAGE 36864
#define MM_SMEM  110592

__device__ __forceinline__ void split_bf16(float a, __nv_bfloat16& hi, __nv_bfloat16& lo) {
    hi = __float2bfloat16_rn(a);
    lo = __float2bfloat16_rn(a - __bfloat162float(hi));
}

__device__ __forceinline__ void mm_compute_stage(uint32_t aA0, uint32_t aA1,
                                                 uint32_t bA0, uint32_t bA1,
                                                 uint32_t bA2, uint32_t bA3,
                                                 float acc[2][8][4]) {
#pragma unroll
    for (int ks = 0; ks < 4; ks++) {
        uint32_t af[2][4], bf[4][4];
        LDMX4(af[0][0], af[0][1], af[0][2], af[0][3], aA0 + ks * 32);
        LDMX4(af[1][0], af[1][1], af[1][2], af[1][3], aA1 + ks * 32);
        LDMX4(bf[0][0], bf[0][1], bf[0][2], bf[0][3], bA0 + ks * 32);
        LDMX4(bf[1][0], bf[1][1], bf[1][2], bf[1][3], bA1 + ks * 32);
        LDMX4(bf[2][0], bf[2][1], bf[2][2], bf[2][3], bA2 + ks * 32);
        LDMX4(bf[3][0], bf[3][1], bf[3][2], bf[3][3], bA3 + ks * 32);
#pragma unroll
        for (int mt = 0; mt < 2; mt++)
#pragma unroll
            for (int nt = 0; nt < 8; nt++) {
                uint32_t b0 = bf[nt >> 1][(nt & 1) * 2];
                uint32_t b1 = bf[nt >> 1][(nt & 1) * 2 + 1];
                MMA16816(acc[mt][nt], af[mt][0], af[mt][1], af[mt][2], af[mt][3], b0, b1);
            }
    }
}

// ================= operand builders =================
__global__ void k_build_a1(const float* __restrict__ x) {
    int gid = blockIdx.x * 256 + threadIdx.x;            // 3200*9216
    int m = gid / 9216, kk = gid - m * 9216;
    int s = kk / 3072, k = kk - s * 3072;
    float a = 0.f;
    if (m < 3136) {
        int c = k >> 10, r = (k >> 5) & 31, q = k & 31;
        int b = m / 196, p = m - b * 196, i = p / 14, j = p - i * 14;
        a = x[((size_t)(b * 3 + c) * 448 + i * 32 + r) * 448 + j * 32 + q];
    }
    __nv_bfloat16 hi, lo; split_bf16(a, hi, lo);
    g_a1[gid] = (s == 1) ? lo : hi;
}
__global__ void k_build_b1(const float* __restrict__ w) {
    int gid = blockIdx.x * 256 + threadIdx.x;            // 2048*9216
    int n = gid / 9216, kk = gid - n * 9216;
    int s = kk / 3072, k = kk - s * 3072;
    __nv_bfloat16 hi, lo; split_bf16(w[(size_t)n * 3072 + k], hi, lo);
    g_b1[gid] = (s == 2) ? lo : hi;
}
__global__ void k_build_w1b(const float* __restrict__ w) {
    int gid = blockIdx.x * 256 + threadIdx.x;            // 128*55296
    int o = gid / 55296, kk = gid - o * 55296;
    int s = kk / 18432, r2 = kk - s * 18432, u = r2 >> 11, c = r2 & 2047;
    __nv_bfloat16 hi, lo; split_bf16(w[(size_t)(o * 2048 + c) * 9 + u], hi, lo);
    g_w1b[gid] = (s == 2) ? lo : hi;
}

// ================= GEMM1: raw = A1' @ B1'^T + bias (HMMA, cp.async 3-stage) =================
// grid (25, 16), 256 thr. Tile 128x128, BK=64, 144 K-tiles.
__global__ __launch_bounds__(256) void k_mm1(const float* __restrict__ bias) {
    extern __shared__ __align__(16) char sm[];
    const int tid = threadIdx.x, wid = tid >> 5, lane = tid & 31;
    const int m0 = blockIdx.x * 128, n0 = blockIdx.y * 128;
    const int wm = wid & 3, wn = wid >> 2;
    const int lr = tid >> 1, lq = tid & 1;
    const int quad = lane >> 3, qr = lane & 7;
    const int g = lane >> 2, tg = lane & 3;

    const char* gA = (const char*)(g_a1 + (size_t)(m0 + lr) * 9216) + lq * 64;
    const char* gB = (const char*)(g_b1 + (size_t)(n0 + lr) * 9216) + lq * 64;
    const uint32_t sbase = smem_addr_u32(sm);
    const uint32_t dstA = sbase + lr * 144 + lq * 64;
    const uint32_t dstB = sbase + 18432 + lr * 144 + lq * 64;

    float acc[2][8][4];
#pragma unroll
    for (int i = 0; i < 2; i++)
#pragma unroll
        for (int j = 0; j < 8; j++)
#pragma unroll
            for (int v = 0; v < 4; v++) acc[i][j][v] = 0.f;

    uint32_t aAddr[2], bAddr[4];
#pragma unroll
    for (int mt = 0; mt < 2; mt++)
        aAddr[mt] = sbase + (wm * 32 + mt * 16 + (quad & 1) * 8 + qr) * 144 + ((quad >> 1) * 8) * 2;
#pragma unroll
    for (int bt = 0; bt < 4; bt++)
        bAddr[bt] = sbase + 18432 + (wn * 64 + bt * 16 + (quad >> 1) * 8 + qr) * 144 + ((quad & 1) * 8) * 2;

    // prologue: stages 0..2
#pragma unroll
    for (int s = 0; s < 3; s++) {
        uint32_t so = s * MM_STAGE;
        const char* pa = gA + s * 128;
        const char* pb = gB + s * 128;
#pragma unroll
        for (int j = 0; j < 4; j++) {
            CPA16(dstA + so + j * 16, pa + j * 16);
            CPA16(dstB + so + j * 16, pb + j * 16);
        }
        CPCOMMIT();
    }

    for (int t = 0; t < 144; t++) {
        CPWAIT2();
        __syncthreads();
        uint32_t so = (t % 3) * MM_STAGE;
        mm_compute_stage(aAddr[0] + so, aAddr[1] + so,
                         bAddr[0] + so, bAddr[1] + so, bAddr[2] + so, bAddr[3] + so, acc);
        __syncthreads();
        if (t + 3 < 144) {
            const char* pa = gA + (t + 3) * 128;
            const char* pb = gB + (t + 3) * 128;
#pragma unroll
            for (int j = 0; j < 4; j++) {
                CPA16(dstA + so + j * 16, pa + j * 16);
                CPA16(dstB + so + j * 16, pb + j * 16);
            }
        }
        CPCOMMIT();
    }

    // epilogue: bias add, write raw (f32) + fused hi/lo split
#pragma unroll
    for (int mt = 0; mt < 2; mt++) {
#pragma unroll
        for (int nt = 0; nt < 8; nt++) {
            int n = n0 + wn * 64 + nt * 8 + tg * 2;
            float bv0 = bias[n], bv1 = bias[n + 1];
            int m1 = m0 + wm * 32 + mt * 16 + g;
#pragma unroll
            for (int h = 0; h < 2; h++) {
                int mm = m1 + h * 8;
                if (mm < 3136) {
                    float v0 = acc[mt][nt][h * 2 + 0] + bv0;
                    float v1 = acc[mt][nt][h * 2 + 1] + bv1;
                    size_t off = (size_t)mm * 2048 + n;
                    g_raw[off] = v0; g_raw[off + 1] = v1;
                    __nv_bfloat16 h0, l0, h1, l1;
                    split_bf16(v0, h0, l0); split_bf16(v1, h1, l1);
                    g_rawhi[off] = h0; g_rawhi[off + 1] = h1;
                    g_rawlo[off] = l0; g_rawlo[off + 1] = l1;
                }
            }
        }
    }
}

// ================= GEMM2: n1 implicit-im2col, split-K=6 (HMMA, cp.async 3-stage) =================
// grid (25, 1, 6), 256 thr. BK=64, 144 K-tiles per split.
__global__ __launch_bounds__(256) void k_mm2() {
    extern __shared__ __align__(16) char sm[];
    const int tid = threadIdx.x, wid = tid >> 5, lane = tid & 31;
    const int m0 = blockIdx.x * 128, sK = blockIdx.z;
    const int wm = wid & 3, wn = wid >> 2;
    const int lr = tid >> 1, lq = tid & 1;
    const int quad = lane >> 3, qr = lane & 7;
    const int g = lane >> 2, tg = lane & 3;

    const int m = m0 + lr;
    int bq = 0, yy = 0, xx = 0;
    const bool mrow_ok = (m < 3136);
    if (mrow_ok) { bq = m / 196; int pp = m - bq * 196; yy = pp / 14; xx = pp - yy * 14; }
    const char* gBw = (const char*)(g_w1b + (size_t)lr * 55296) + lq * 64;

    const uint32_t sbase = smem_addr_u32(sm);
    const uint32_t dstA = sbase + lr * 144 + lq * 64;
    const uint32_t dstB = sbase + 18432 + lr * 144 + lq * 64;

    float acc[2][8][4];
#pragma unroll
    for (int i = 0; i < 2; i++)
#pragma unroll
        for (int j = 0; j < 8; j++)
#pragma unroll
            for (int v = 0; v < 4; v++) acc[i][j][v] = 0.f;

    uint32_t aAddr[2], bAddr[4];
#pragma unroll
    for (int mt = 0; mt < 2; mt++)
        aAddr[mt] = sbase + (wm * 32 + mt * 16 + (quad & 1) * 8 + qr) * 144 + ((quad >> 1) * 8) * 2;
#pragma unroll
    for (int bt = 0; bt < 4; bt++)
        bAddr[bt] = sbase + 18432 + (wn * 64 + bt * 16 + (quad >> 1) * 8 + qr) * 144 + ((quad & 1) * 8) * 2;

    const int t0 = sK * 144;

    // loader for tile (global index gT) into stage so
#define MM2_LOAD(gT, so) do { \
        int _sp = (gT) / 288, _rem = (gT) - _sp * 288; \
        int _u = _rem >> 5, _c0 = (_rem & 31) << 6; \
        int _ys = yy + _u / 3 - 1, _xs = xx + (_u % 3) - 1; \
        bool _ok = mrow_ok && ((unsigned)_ys < 14u) && ((unsigned)_xs < 14u); \
        int _ysc = _ok ? _ys : 0, _xsc = _ok ? _xs : 0; \
        const __nv_bfloat16* _rs = (_sp == 1) ? g_rawlo : g_rawhi; \
        const char* _pa = (const char*)(_rs + (size_t)(bq * 196 + _ysc * 14 + _xsc) * 2048 + _c0) + lq * 64; \
        const char* _pb = gBw + (size_t)(gT) * 128; \
        uint32_t _okb = _ok ? 16u : 0u; \
        _Pragma("unroll") \
        for (int _j = 0; _j < 4; _j++) { \
            CPA16Z(dstA + (so) + _j * 16, _pa + _j * 16, _okb); \
            CPA16(dstB + (so) + _j * 16, _pb + _j * 16); \
        } \
    } while (0)

#pragma unroll
    for (int s = 0; s < 3; s++) {
        MM2_LOAD(t0 + s, s * MM_STAGE);
        CPCOMMIT();
    }

    for (int t = 0; t < 144; t++) {
        CPWAIT2();
        __syncthreads();
        uint32_t so = (t % 3) * MM_STAGE;
        mm_compute_stage(aAddr[0] + so, aAddr[1] + so,
                         bAddr[0] + so, bAddr[1] + so, bAddr[2] + so, bAddr[3] + so, acc);
        __syncthreads();
        if (t + 3 < 144) {
            MM2_LOAD(t0 + t + 3, so);
        }
        CPCOMMIT();
    }
#undef MM2_LOAD

#pragma unroll
    for (int mt = 0; mt < 2; mt++) {
#pragma unroll
        for (int nt = 0; nt < 8; nt++) {
            int n = wn * 64 + nt * 8 + tg * 2;
            int m1 = m0 + wm * 32 + mt * 16 + g;
#pragma unroll
            for (int h = 0; h < 2; h++) {
                int mm = m1 + h * 8;
                if (mm < 3136) {
                    float* dst = g_y1p + ((size_t)sK * 3136 + mm) * 128 + n;
                    dst[0] = acc[mt][nt][h * 2 + 0];
                    dst[1] = acc[mt][nt][h * 2 + 1];
                }
            }
        }
    }
}

__global__ void k_reduce_y1(const float* __restrict__ db) {
    int gid = blockIdx.x * 256 + threadIdx.x; // 401408
    float v = db[gid & 127];
#pragma unroll
    for (int s = 0; s < 6; s++) v += g_y1p[(size_t)s * 401408 + gid];
    g_y1[gid] = fmaxf(v, 0.f);
}

// ================= tail (R7-passing versions) =================
__global__ void k_transpose_bbw(const float* __restrict__ src) {
    __shared__ float tile[32][33];
    int c0 = blockIdx.x * 32, r0 = blockIdx.y * 32;
    int tx = threadIdx.x, ty = threadIdx.y;
    for (int i = ty; i < 32; i += 8)
        tile[i][tx] = src[(size_t)(r0 + i) * 3072 + c0 + tx];
    __syncthreads();
    for (int i = ty; i < 32; i += 8)
        g_bbwt[(size_t)(c0 + i) * 2048 + r0 + tx] = tile[tx][i];
}
__global__ void k_repack_w2(const float* __restrict__ src) {
    int gid = blockIdx.x * 256 + threadIdx.x;
    int k = gid >> 7, o = gid & 127, u = k >> 7, c = k & 127;
    g_w2t[gid] = src[(o * 128 + c) * 9 + u];
}
__global__ void k_repack_w3(const float* __restrict__ src) {
    int gid = blockIdx.x * 256 + threadIdx.x;
    int k = gid >> 7, o = gid & 127, u = k >> 7, c = k & 127;
    g_w3t[gid] = src[(o * 128 + c) * 9 + u];
}
template <int IN, int OUTW>
__device__ __forceinline__ void conv_s2_body(const float* __restrict__ yin,
                                             const float* __restrict__ wt,
                                             const float* __restrict__ bias,
                                             float* __restrict__ yout) {
    const int b = blockIdx.x, oy = blockIdx.y, o = threadIdx.x;
    __shared__ float s[3][IN][128];
#pragma unroll
    for (int ky = 0; ky < 3; ky++) {
        int iy = oy * 2 - 1 + ky;
        for (int t = 0; t < IN; t++)
            s[ky][t][o] = (iy >= 0 && iy < IN) ? yin[((size_t)(b * IN + iy) * IN + t) * 128 + o] : 0.f;
    }
    __syncthreads();
    float acc[OUTW];
#pragma unroll
    for (int ox = 0; ox < OUTW; ox++) acc[ox] = bias[o];
#pragma unroll
    for (int ky = 0; ky < 3; ky++)
#pragma unroll
        for (int kx = 0; kx < 3; kx++) {
            const float* wp = wt + (size_t)((ky * 3 + kx) * 128) * 128 + o;
            for (int c = 0; c < 128; c++) {
                float wv = wp[(size_t)c * 128];
#pragma unroll
                for (int ox = 0; ox < OUTW; ox++) {
                    int xs = ox * 2 + kx - 1;
                    if (xs >= 0 && xs < IN) acc[ox] += s[ky][xs][c] * wv;
                }
            }
        }
#pragma unroll
    for (int ox = 0; ox < OUTW; ox++)
        yout[((size_t)(b * OUTW + oy) * OUTW + ox) * 128 + o] = fmaxf(acc[ox], 0.f);
}
__global__ void k_conv_n2(const float* __restrict__ b) { conv_s2_body<14, 7>(g_y1, g_w2t, b, g_y2); }
__global__ void k_conv_n3(const float* __restrict__ b) { conv_s2_body<7, 4>(g_y2, g_w3t, b, g_y3); }

__global__ void k_scores(const float* __restrict__ t1w, const float* __restrict__ t1b,
                         const float* __restrict__ t2w, const float* __restrict__ t2b,
                         const float* __restrict__ t3w, const float* __restrict__ t3b) {
    int gid = blockIdx.x * 256 + threadIdx.x;
    if (gid >= 16 * ANCH_N) return;
    int b = gid / ANCH_N, r = gid - b * ANCH_N;
    const float *f, *w; float bv;
    if (r < 1176) {
        int a = r / 196, p = r - a * 196;
        f = g_y1 + (size_t)(b * 196 + p) * 128; w = t1w + a * 128; bv = t1b[a];
    } else if (r < 1470) {
        int rr = r - 1176, a = rr / 49, p = rr - a * 49;
        f = g_y2 + (size_t)(b * 49 + p) * 128; w = t2w + a * 128; bv = t2b[a];
    } else {
        int rr = r - 1470, a = rr >> 4, p = rr & 15;
        f = g_y3 + (size_t)(b * 16 + p) * 128; w = t3w + a * 128; bv = t3b[a];
    }
    float acc = bv;
#pragma unroll 4
    for (int c = 0; c < 128; c++) acc += f[c] * w[c];
    g_rpn[gid] = acc;
}

__global__ void k_nms(const int* __restrict__ an) {
    const int b = blockIdx.x, tid = threadIdx.x;
    __shared__ float sc[ANCH_N];
    __shared__ int vld[ANCH_N];
    __shared__ float rv[256];
    __shared__ int ri[256];
    __shared__ int pick;
    for (int i = tid; i < ANCH_N; i += 256) { sc[i] = g_rpn[b * ANCH_N + i]; vld[i] = 1; }
    __syncthreads();
    for (int it = 0; it < 4; it++) {
        float v = -3.0e38f; int idx = ANCH_N;
        for (int i = tid; i < ANCH_N; i += 256)
            if (vld[i]) { float sv = sc[i]; if (sv > v) { v = sv; idx = i; } }
        rv[tid] = v; ri[tid] = idx;
        __syncthreads();
        for (int st = 128; st; st >>= 1) {
            if (tid < st) {
                float v2 = rv[tid + st]; int i2 = ri[tid + st];
                if (v2 > rv[tid] || (v2 == rv[tid] && i2 < ri[tid])) { rv[tid] = v2; ri[tid] = i2; }
            }
            __syncthreads();
        }
        if (tid == 0) { pick = ri[0]; g_top[b * 4 + it] = ri[0]; }
        __syncthreads();
        int pi = pick;
        float py0 = (float)an[pi * 4], px0 = (float)an[pi * 4 + 1];
        float py1 = (float)an[pi * 4 + 2], px1 = (float)an[pi * 4 + 3];
        float pa = (py1 - py0) * (px1 - px0);
        for (int i = tid; i < ANCH_N; i += 256) {
            float y0 = (float)an[i * 4], x0 = (float)an[i * 4 + 1];
            float y1 = (float)an[i * 4 + 2], x1 = (float)an[i * 4 + 3];
            float ih = fminf(y1, py1) - fmaxf(y0, py0);
            float iw = fminf(x1, px1) - fmaxf(x0, px0);
            float inter = (ih < 0.f || iw < 0.f) ? 0.f : ih * iw;
            float iou = inter / ((y1 - y0) * (x1 - x0) + pa - inter);
            if (iou >= 0.25f) vld[i] = 0;
        }
        __syncthreads();
    }
}

__global__ void k_abar(const float* __restrict__ x, const int* __restrict__ an) {
    int gid = blockIdx.x * 256 + threadIdx.x; // 196608
    int p = gid / 3072, k = gid - p * 3072;
    int c = k >> 10, ky = (k >> 5) & 31, kx = k & 31;
    int b = p >> 2;
    int ai = g_top[p];
    int y0 = an[ai * 4], x0 = an[ai * 4 + 1], y1 = an[ai * 4 + 2], x1 = an[ai * 4 + 3];
    float hm1 = (float)(y1 - y0 - 1), wm1 = (float)(x1 - x0 - 1);
    int ix0[7], ix1[7]; float wx[7];
#pragma unroll
    for (int tj = 0; tj < 7; tj++) {
        float sx = __fdiv_rn((float)(tj * 32 + kx) * wm1, 223.f);
        float fx = floorf(sx);
        wx[tj] = sx - fx;
        int i0 = x0 + (int)fx;
        ix0[tj] = i0 - 224;
        ix1[tj] = min(i0 + 1, x1 - 1) - 224;
    }
    const float* xb = x + (size_t)(b * 3 + c) * 200704;
    float acc = 0.f;
#pragma unroll
    for (int ti = 0; ti < 7; ti++) {
        float sy = __fdiv_rn((float)(ti * 32 + ky) * hm1, 223.f);
        float fy = floorf(sy);
        float wy = sy - fy;
        int ry0 = y0 + (int)fy - 224;
        int ry1 = min(y0 + (int)fy + 1, y1 - 1) - 224;
        bool v0 = (unsigned)ry0 < 448u, v1 = (unsigned)ry1 < 448u;
#pragma unroll
        for (int tj = 0; tj < 7; tj++) {
            int cx0 = ix0[tj], cx1 = ix1[tj];
            bool u0 = (unsigned)cx0 < 448u, u1 = (unsigned)cx1 < 448u;
            float v00 = (v0 && u0) ? xb[ry0 * 448 + cx0] : 0.f;
            float v01 = (v0 && u1) ? xb[ry0 * 448 + cx1] : 0.f;
            float v10 = (v1 && u0) ? xb[ry1 * 448 + cx0] : 0.f;
            float v11 = (v1 && u1) ? xb[ry1 * 448 + cx1] : 0.f;
            float w = wx[tj];
            float top = v00 * (1.f - w) + v01 * w;
            float bot = v10 * (1.f - w) + v11 * w;
            acc += top * (1.f - wy) + bot * wy;
        }
    }
    g_abar[gid] = acc * (1.f / 49.f);
}

__device__ __forceinline__ void mac_tile(const float* As, const float* Bs,
                                         float acc[4][8], int ty, int tx) {
#pragma unroll
    for (int kk = 0; kk < 32; kk++) {
        float a0 = As[kk * 65 + ty * 4 + 0];
        float a1 = As[kk * 65 + ty * 4 + 1];
        float a2 = As[kk * 65 + ty * 4 + 2];
        float a3 = As[kk * 65 + ty * 4 + 3];
        float4 b0 = *(const float4*)&Bs[kk * 128 + tx * 8];
        float4 b1 = *(const float4*)&Bs[kk * 128 + tx * 8 + 4];
        float bv[8] = {b0.x, b0.y, b0.z, b0.w, b1.x, b1.y, b1.z, b1.w};
#pragma unroll
        for (int j = 0; j < 8; j++) {
            acc[0][j] += a0 * bv[j];
            acc[1][j] += a1 * bv[j];
            acc[2][j] += a2 * bv[j];
            acc[3][j] += a3 * bv[j];
        }
    }
}
__global__ __launch_bounds__(256, 3) void k_gemm_part() {
    __shared__ float As[32 * 65];
    __shared__ float Bs[32 * 128];
    const int tid = threadIdx.x;
    const int n0 = blockIdx.y * 128, s = blockIdx.z;
    const int kl = tid & 31, mr = tid >> 5;
    const int ty = tid >> 4, tx = tid & 15;
    float acc[4][8];
#pragma unroll
    for (int a = 0; a < 4; a++)
#pragma unroll
        for (int q = 0; q < 8; q++) acc[a][q] = 0.f;
    for (int kt = s * 12; kt < s * 12 + 12; kt++) {
#pragma unroll
        for (int l = 0; l < 8; l++)
            As[kl * 65 + mr + l * 8] = g_abar[(size_t)(mr + l * 8) * 3072 + kt * 32 + kl];
        const float* bsrc = g_bbwt + (size_t)kt * 65536 + n0;
#pragma unroll
        for (int l = 0; l < 16; l++) {
            int e = tid + l * 256;
            Bs[e] = bsrc[(e >> 7) * 2048 + (e & 127)];
        }
        __syncthreads();
        mac_tile(As, Bs, acc, ty, tx);
        __syncthreads();
    }
#pragma unroll
    for (int im = 0; im < 4; im++) {
        float* dst = g_pfp + (size_t)(s * 64 + ty * 4 + im) * 2048 + n0 + tx * 8;
#pragma unroll
        for (int jn = 0; jn < 8; jn++) dst[jn] = acc[im][jn];
    }
}
__global__ void k_reduce_part(const float* __restrict__ bb) {
    int gid = blockIdx.x * 256 + threadIdx.x; // 131072
    float v = bb[gid & 2047];
#pragma unroll
    for (int s = 0; s < 8; s++) v += g_pfp[(size_t)s * 131072 + gid];
    g_pf[gid] = v;
}
__global__ void k_rawfeat() {
    int gid = blockIdx.x * 256 + threadIdx.x; // 32768
    int b = gid >> 11, o = gid & 2047;
    float v = 0.f;
    for (int p = 0; p < 196; p++) v += g_raw[(size_t)(b * 196 + p) * 2048 + o];
    g_rf[gid] = v * (1.f / 196.f);
}
__global__ void k_classifier(const float* __restrict__ cw, const float* __restrict__ cb,
                             float* __restrict__ out) {
    int w = blockIdx.x * 8 + (threadIdx.x >> 5);
    int lane = threadIdx.x & 31;
    int b = w / 200, cls = w - b * 200;
    const float* wr = cw + (size_t)cls * 10240;
    const float* pf = g_pf + (size_t)b * 4 * 2048;
    const float* rf = g_rf + (size_t)b * 2048;
    float acc = 0.f;
    for (int j = lane; j < 8192; j += 32) acc += pf[j] * wr[j];
    for (int j = lane; j < 2048; j += 32) acc += rf[j] * wr[8192 + j];
#pragma unroll
    for (int st = 16; st; st >>= 1) acc += __shfl_xor_sync(0xffffffffu, acc, st);
    if (lane == 0) out[w] = acc + cb[cls];
}

// ================= launch =================
extern "C" void kernel_launch(void* const* d_in, const int* in_sizes, int n_in,
                              void* d_out, int out_size) {
    const float* x     = (const float*)d_in[0];
    const float* bb_w  = (const float*)d_in[1];
    const float* bb_b  = (const float*)d_in[2];
    const float* n1_dw = (const float*)d_in[3];
    const float* n1_db = (const float*)d_in[4];
    const float* n1_tw = (const float*)d_in[5];
    const float* n1_tb = (const float*)d_in[6];
    const float* n2_dw = (const float*)d_in[7];
    const float* n2_db = (const float*)d_in[8];
    const float* n2_tw = (const float*)d_in[9];
    const float* n2_tb = (const float*)d_in[10];
    const float* n3_dw = (const float*)d_in[11];
    const float* n3_db = (const float*)d_in[12];
    const float* n3_tw = (const float*)d_in[13];
    const float* n3_tb = (const float*)d_in[14];
    const float* cn_w  = (const float*)d_in[15];
    const float* cn_b  = (const float*)d_in[16];
    const int*   anch  = (const int*)d_in[17];
    float* out = (float*)d_out;

    cudaFuncSetAttribute(k_mm1, cudaFuncAttributeMaxDynamicSharedMemorySize, MM_SMEM);
    cudaFuncSetAttribute(k_mm2, cudaFuncAttributeMaxDynamicSharedMemorySize, MM_SMEM);

    k_build_a1<<<115200, 256>>>(x);
    k_build_b1<<<73728, 256>>>(bb_w);
    k_build_w1b<<<27648, 256>>>(n1_dw);
    k_transpose_bbw<<<dim3(96, 64), dim3(32, 8)>>>(bb_w);
    k_repack_w2<<<576, 256>>>(n2_dw);
    k_repack_w3<<<576, 256>>>(n3_dw);
    k_mm1<<<dim3(25, 16), 256, MM_SMEM>>>(bb_b);
    k_mm2<<<dim3(25, 1, 6), 256, MM_SMEM>>>();
    k_reduce_y1<<<1568, 256>>>(n1_db);
    k_conv_n2<<<dim3(16, 7), 128>>>(n2_db);
    k_conv_n3<<<dim3(16, 4), 128>>>(n3_db);
    k_scores<<<101, 256>>>(n1_tw, n1_tb, n2_tw, n2_tb, n3_tw, n3_tb);
    k_nms<<<16, 256>>>(anch);
    k_abar<<<768, 256>>>(x, anch);
    k_gemm_part<<<dim3(1, 16, 8), 256>>>();
    k_reduce_part<<<512, 256>>>(bb_b);
    k_rawfeat<<<128, 256>>>();
    k_classifier<<<400, 256>>>(cn_w, cn_b, out);
}

// round 16
// speedup vs baseline: 1.8814x; 1.1198x over previous
#include <cuda_runtime.h>
#include <cuda_bf16.h>
#include <cstdint>
#include <stdint.h>
#include <math.h>

#define ANCH_N 1614

// ================= static device scratch =================
__device__ float g_bbwt[3072 * 2048];
__device__ float g_raw [3136 * 2048];
__device__ __nv_bfloat16 g_a1[3200 * 9216];
__device__ __nv_bfloat16 g_b1[2048 * 9216];
__device__ __nv_bfloat16 g_rawhi[3136 * 2048];
__device__ __nv_bfloat16 g_rawlo[3136 * 2048];
__device__ __nv_bfloat16 g_w1b[128 * 55296];
__device__ float g_y1p [6 * 3136 * 128];
__device__ float g_y1  [3136 * 128];
__device__ float g_w2t [1152 * 128];
__device__ float g_w3t [1152 * 128];
__device__ float g_y2  [16 * 49 * 128];
__device__ float g_y3  [16 * 16 * 128];
__device__ float g_rpn [16 * ANCH_N];
__device__ int   g_top [64];
__device__ float g_abar[64 * 3072];
__device__ float g_pfp [8 * 64 * 2048];
__device__ float g_pf  [64 * 2048];
__device__ float g_rf  [16 * 2048];

// ================= warp-MMA helpers (base-target instructions only) =================
__device__ __forceinline__ uint32_t smem_addr_u32(const void* p) {
    uint32_t a;
    asm("{ .reg .u64 t; cvta.to.shared.u64 t, %1; cvt.u32.u64 %0, t; }" : "=r"(a) : "l"(p));
    return a;
}
#define LDMX4(r0, r1, r2, r3, a) \
    asm volatile("ldmatrix.sync.aligned.m8n8.x4.shared.b16 {%0,%1,%2,%3}, [%4];" \
                 : "=r"(r0), "=r"(r1), "=r"(r2), "=r"(r3) : "r"(a))
#define MMA16816(d, a0, a1, a2, a3, b0, b1) \
    asm volatile("mma.sync.aligned.m16n8k16.row.col.f32.bf16.bf16.f32 " \
                 "{%0,%1,%2,%3}, {%4,%5,%6,%7}, {%8,%9}, {%0,%1,%2,%3};" \
                 : "+f"((d)[0]), "+f"((d)[1]), "+f"((d)[2]), "+f"((d)[3]) \
                 : "r"(a0), "r"(a1), "r"(a2), "r"(a3), "r"(b0), "r"(b1))
#define CPA16(dst, src) \
    asm volatile("cp.async.ca.shared.global [%0], [%1], 16;" :: "r"(dst), "l"(src))
#define CPA16Z(dst, src, okbytes) \
    asm volatile("cp.async.ca.shared.global [%0], [%1], 16, %2;" :: "r"(dst), "l"(src), "r"(okbytes))
#define CPCOMMIT() asm volatile("cp.async.commit_group;" ::: "memory")
#define CPWAIT2()  asm volatile("cp.async.wait_group 2;" ::: "memory")

// stage: A 128x72 bf16 (18432 B) + B 128x72 bf16 -> 36864 B; 3 stages = 110592 B
#define MM_STAGE 36864
#define MM_SMEM  110592

__device__ __forceinline__ void split_bf16(float a, __nv_bfloat16& hi, __nv_bfloat16& lo) {
    hi = __float2bfloat16_rn(a);
    lo = __float2bfloat16_rn(a - __bfloat162float(hi));
}

__device__ __forceinline__ void mm_compute_stage(uint32_t aA0, uint32_t aA1,
                                                 uint32_t bA0, uint32_t bA1,
                                                 uint32_t bA2, uint32_t bA3,
                                                 float acc[2][8][4]) {
#pragma unroll
    for (int ks = 0; ks < 4; ks++) {
        uint32_t af[2][4], bf[4][4];
        LDMX4(af[0][0], af[0][1], af[0][2], af[0][3], aA0 + ks * 32);
        LDMX4(af[1][0], af[1][1], af[1][2], af[1][3], aA1 + ks * 32);
        LDMX4(bf[0][0], bf[0][1], bf[0][2], bf[0][3], bA0 + ks * 32);
        LDMX4(bf[1][0], bf[1][1], bf[1][2], bf[1][3], bA1 + ks * 32);
        LDMX4(bf[2][0], bf[2][1], bf[2][2], bf[2][3], bA2 + ks * 32);
        LDMX4(bf[3][0], bf[3][1], bf[3][2], bf[3][3], bA3 + ks * 32);
#pragma unroll
        for (int mt = 0; mt < 2; mt++)
#pragma unroll
            for (int nt = 0; nt < 8; nt++) {
                uint32_t b0 = bf[nt >> 1][(nt & 1) * 2];
                uint32_t b1 = bf[nt >> 1][(nt & 1) * 2 + 1];
                MMA16816(acc[mt][nt], af[mt][0], af[mt][1], af[mt][2], af[mt][3], b0, b1);
            }
    }
}

// ================= operand builders (deduped: 1 load -> 3 stores) =================
__global__ void k_build_a1(const float* __restrict__ x) {
    int gid = blockIdx.x * 256 + threadIdx.x;            // 3200*3072
    int m = gid / 3072, k = gid - m * 3072;
    float a = 0.f;
    if (m < 3136) {
        int c = k >> 10, r = (k >> 5) & 31, q = k & 31;
        int b = m / 196, p = m - b * 196, i = p / 14, j = p - i * 14;
        a = x[((size_t)(b * 3 + c) * 448 + i * 32 + r) * 448 + j * 32 + q];
    }
    __nv_bfloat16 hi, lo; split_bf16(a, hi, lo);
    size_t base = (size_t)m * 9216 + k;
    g_a1[base] = hi; g_a1[base + 3072] = lo; g_a1[base + 6144] = hi;
}
__global__ void k_build_b1(const float* __restrict__ w) {
    int gid = blockIdx.x * 256 + threadIdx.x;            // 2048*3072
    int n = gid / 3072, k = gid - n * 3072;
    __nv_bfloat16 hi, lo; split_bf16(w[(size_t)n * 3072 + k], hi, lo);
    size_t base = (size_t)n * 9216 + k;
    g_b1[base] = hi; g_b1[base + 3072] = hi; g_b1[base + 6144] = lo;
}
__global__ void k_build_w1b(const float* __restrict__ w) {
    int gid = blockIdx.x * 256 + threadIdx.x;            // 128*18432
    int o = gid / 18432, r2 = gid - o * 18432, u = r2 >> 11, c = r2 & 2047;
    __nv_bfloat16 hi, lo; split_bf16(w[(size_t)(o * 2048 + c) * 9 + u], hi, lo);
    size_t base = (size_t)o * 55296 + r2;
    g_w1b[base] = hi; g_w1b[base + 18432] = hi; g_w1b[base + 36864] = lo;
}

// ================= GEMM1: raw = A1' @ B1'^T + bias (HMMA, cp.async 3-stage) =================
// grid (25, 16), 256 thr, 2 CTAs/SM. Tile 128x128, BK=64, 144 K-tiles.
__global__ __launch_bounds__(256, 2) void k_mm1(const float* __restrict__ bias) {
    extern __shared__ __align__(16) char sm[];
    const int tid = threadIdx.x, wid = tid >> 5, lane = tid & 31;
    const int m0 = blockIdx.x * 128, n0 = blockIdx.y * 128;
    const int wm = wid & 3, wn = wid >> 2;
    const int lr = tid >> 1, lq = tid & 1;
    const int quad = lane >> 3, qr = lane & 7;
    const int g = lane >> 2, tg = lane & 3;

    const char* gA = (const char*)(g_a1 + (size_t)(m0 + lr) * 9216) + lq * 64;
    const char* gB = (const char*)(g_b1 + (size_t)(n0 + lr) * 9216) + lq * 64;
    const uint32_t sbase = smem_addr_u32(sm);
    const uint32_t dstA = sbase + lr * 144 + lq * 64;
    const uint32_t dstB = sbase + 18432 + lr * 144 + lq * 64;

    float acc[2][8][4];
#pragma unroll
    for (int i = 0; i < 2; i++)
#pragma unroll
        for (int j = 0; j < 8; j++)
#pragma unroll
            for (int v = 0; v < 4; v++) acc[i][j][v] = 0.f;

    uint32_t aAddr[2], bAddr[4];
#pragma unroll
    for (int mt = 0; mt < 2; mt++)
        aAddr[mt] = sbase + (wm * 32 + mt * 16 + (quad & 1) * 8 + qr) * 144 + ((quad >> 1) * 8) * 2;
#pragma unroll
    for (int bt = 0; bt < 4; bt++)
        bAddr[bt] = sbase + 18432 + (wn * 64 + bt * 16 + (quad >> 1) * 8 + qr) * 144 + ((quad & 1) * 8) * 2;

    // prologue: stages 0..2
#pragma unroll
    for (int s = 0; s < 3; s++) {
        uint32_t so = s * MM_STAGE;
        const char* pa = gA + s * 128;
        const char* pb = gB + s * 128;
#pragma unroll
        for (int j = 0; j < 4; j++) {
            CPA16(dstA + so + j * 16, pa + j * 16);
            CPA16(dstB + so + j * 16, pb + j * 16);
        }
        CPCOMMIT();
    }

    for (int t = 0; t < 144; t++) {
        CPWAIT2();
        __syncthreads();
        uint32_t so = (t % 3) * MM_STAGE;
        mm_compute_stage(aAddr[0] + so, aAddr[1] + so,
                         bAddr[0] + so, bAddr[1] + so, bAddr[2] + so, bAddr[3] + so, acc);
        __syncthreads();
        if (t + 3 < 144) {
            const char* pa = gA + (t + 3) * 128;
            const char* pb = gB + (t + 3) * 128;
#pragma unroll
            for (int j = 0; j < 4; j++) {
                CPA16(dstA + so + j * 16, pa + j * 16);
                CPA16(dstB + so + j * 16, pb + j * 16);
            }
        }
        CPCOMMIT();
    }

    // epilogue: bias add, write raw (f32) + fused hi/lo split
#pragma unroll
    for (int mt = 0; mt < 2; mt++) {
#pragma unroll
        for (int nt = 0; nt < 8; nt++) {
            int n = n0 + wn * 64 + nt * 8 + tg * 2;
            float bv0 = bias[n], bv1 = bias[n + 1];
            int m1 = m0 + wm * 32 + mt * 16 + g;
#pragma unroll
            for (int h = 0; h < 2; h++) {
                int mm = m1 + h * 8;
                if (mm < 3136) {
                    float v0 = acc[mt][nt][h * 2 + 0] + bv0;
                    float v1 = acc[mt][nt][h * 2 + 1] + bv1;
                    size_t off = (size_t)mm * 2048 + n;
                    g_raw[off] = v0; g_raw[off + 1] = v1;
                    __nv_bfloat16 h0, l0, h1, l1;
                    split_bf16(v0, h0, l0); split_bf16(v1, h1, l1);
                    g_rawhi[off] = h0; g_rawhi[off + 1] = h1;
                    g_rawlo[off] = l0; g_rawlo[off + 1] = l1;
                }
            }
        }
    }
}

// ================= GEMM2: n1 implicit-im2col, split-K=6 (HMMA, cp.async 3-stage) =================
// grid (25, 1, 6), 256 thr, 2 CTAs/SM. BK=64, 144 K-tiles per split.
__global__ __launch_bounds__(256, 2) void k_mm2() {
    extern __shared__ __align__(16) char sm[];
    const int tid = threadIdx.x, wid = tid >> 5, lane = tid & 31;
    const int m0 = blockIdx.x * 128, sK = blockIdx.z;
    const int wm = wid & 3, wn = wid >> 2;
    const int lr = tid >> 1, lq = tid & 1;
    const int quad = lane >> 3, qr = lane & 7;
    const int g = lane >> 2, tg = lane & 3;

    const int m = m0 + lr;
    int bq = 0, yy = 0, xx = 0;
    const bool mrow_ok = (m < 3136);
    if (mrow_ok) { bq = m / 196; int pp = m - bq * 196; yy = pp / 14; xx = pp - yy * 14; }
    const char* gBw = (const char*)(g_w1b + (size_t)lr * 55296) + lq * 64;

    const uint32_t sbase = smem_addr_u32(sm);
    const uint32_t dstA = sbase + lr * 144 + lq * 64;
    const uint32_t dstB = sbase + 18432 + lr * 144 + lq * 64;

    float acc[2][8][4];
#pragma unroll
    for (int i = 0; i < 2; i++)
#pragma unroll
        for (int j = 0; j < 8; j++)
#pragma unroll
            for (int v = 0; v < 4; v++) acc[i][j][v] = 0.f;

    uint32_t aAddr[2], bAddr[4];
#pragma unroll
    for (int mt = 0; mt < 2; mt++)
        aAddr[mt] = sbase + (wm * 32 + mt * 16 + (quad & 1) * 8 + qr) * 144 + ((quad >> 1) * 8) * 2;
#pragma unroll
    for (int bt = 0; bt < 4; bt++)
        bAddr[bt] = sbase + 18432 + (wn * 64 + bt * 16 + (quad >> 1) * 8 + qr) * 144 + ((quad & 1) * 8) * 2;

    const int t0 = sK * 144;

#define MM2_LOAD(gT, so) do { \
        int _sp = (gT) / 288, _rem = (gT) - _sp * 288; \
        int _u = _rem >> 5, _c0 = (_rem & 31) << 6; \
        int _ys = yy + _u / 3 - 1, _xs = xx + (_u % 3) - 1; \
        bool _ok = mrow_ok && ((unsigned)_ys < 14u) && ((unsigned)_xs < 14u); \
        int _ysc = _ok ? _ys : 0, _xsc = _ok ? _xs : 0; \
        const __nv_bfloat16* _rs = (_sp == 1) ? g_rawlo : g_rawhi; \
        const char* _pa = (const char*)(_rs + (size_t)(bq * 196 + _ysc * 14 + _xsc) * 2048 + _c0) + lq * 64; \
        const char* _pb = gBw + (size_t)(gT) * 128; \
        uint32_t _okb = _ok ? 16u : 0u; \
        _Pragma("unroll") \
        for (int _j = 0; _j < 4; _j++) { \
            CPA16Z(dstA + (so) + _j * 16, _pa + _j * 16, _okb); \
            CPA16(dstB + (so) + _j * 16, _pb + _j * 16); \
        } \
    } while (0)

#pragma unroll
    for (int s = 0; s < 3; s++) {
        MM2_LOAD(t0 + s, s * MM_STAGE);
        CPCOMMIT();
    }

    for (int t = 0; t < 144; t++) {
        CPWAIT2();
        __syncthreads();
        uint32_t so = (t % 3) * MM_STAGE;
        mm_compute_stage(aAddr[0] + so, aAddr[1] + so,
                         bAddr[0] + so, bAddr[1] + so, bAddr[2] + so, bAddr[3] + so, acc);
        __syncthreads();
        if (t + 3 < 144) {
            MM2_LOAD(t0 + t + 3, so);
        }
        CPCOMMIT();
    }
#undef MM2_LOAD

#pragma unroll
    for (int mt = 0; mt < 2; mt++) {
#pragma unroll
        for (int nt = 0; nt < 8; nt++) {
            int n = wn * 64 + nt * 8 + tg * 2;
            int m1 = m0 + wm * 32 + mt * 16 + g;
#pragma unroll
            for (int h = 0; h < 2; h++) {
                int mm = m1 + h * 8;
                if (mm < 3136) {
                    float* dst = g_y1p + ((size_t)sK * 3136 + mm) * 128 + n;
                    dst[0] = acc[mt][nt][h * 2 + 0];
                    dst[1] = acc[mt][nt][h * 2 + 1];
                }
            }
        }
    }
}

__global__ void k_reduce_y1(const float* __restrict__ db) {
    int gid = blockIdx.x * 256 + threadIdx.x; // 401408
    float v = db[gid & 127];
#pragma unroll
    for (int s = 0; s < 6; s++) v += g_y1p[(size_t)s * 401408 + gid];
    g_y1[gid] = fmaxf(v, 0.f);
}

// ================= tail (R7-passing versions) =================
__global__ void k_transpose_bbw(const float* __restrict__ src) {
    __shared__ float tile[32][33];
    int c0 = blockIdx.x * 32, r0 = blockIdx.y * 32;
    int tx = threadIdx.x, ty = threadIdx.y;
    for (int i = ty; i < 32; i += 8)
        tile[i][tx] = src[(size_t)(r0 + i) * 3072 + c0 + tx];
    __syncthreads();
    for (int i = ty; i < 32; i += 8)
        g_bbwt[(size_t)(c0 + i) * 2048 + r0 + tx] = tile[tx][i];
}
__global__ void k_repack_w2(const float* __restrict__ src) {
    int gid = blockIdx.x * 256 + threadIdx.x;
    int k = gid >> 7, o = gid & 127, u = k >> 7, c = k & 127;
    g_w2t[gid] = src[(o * 128 + c) * 9 + u];
}
__global__ void k_repack_w3(const float* __restrict__ src) {
    int gid = blockIdx.x * 256 + threadIdx.x;
    int k = gid >> 7, o = gid & 127, u = k >> 7, c = k & 127;
    g_w3t[gid] = src[(o * 128 + c) * 9 + u];
}
template <int IN, int OUTW>
__device__ __forceinline__ void conv_s2_body(const float* __restrict__ yin,
                                             const float* __restrict__ wt,
                                             const float* __restrict__ bias,
                                             float* __restrict__ yout) {
    const int b = blockIdx.x, oy = blockIdx.y, o = threadIdx.x;
    __shared__ float s[3][IN][128];
#pragma unroll
    for (int ky = 0; ky < 3; ky++) {
        int iy = oy * 2 - 1 + ky;
        for (int t = 0; t < IN; t++)
            s[ky][t][o] = (iy >= 0 && iy < IN) ? yin[((size_t)(b * IN + iy) * IN + t) * 128 + o] : 0.f;
    }
    __syncthreads();
    float acc[OUTW];
#pragma unroll
    for (int ox = 0; ox < OUTW; ox++) acc[ox] = bias[o];
#pragma unroll
    for (int ky = 0; ky < 3; ky++)
#pragma unroll
        for (int kx = 0; kx < 3; kx++) {
            const float* wp = wt + (size_t)((ky * 3 + kx) * 128) * 128 + o;
            for (int c = 0; c < 128; c++) {
                float wv = wp[(size_t)c * 128];
#pragma unroll
                for (int ox = 0; ox < OUTW; ox++) {
                    int xs = ox * 2 + kx - 1;
                    if (xs >= 0 && xs < IN) acc[ox] += s[ky][xs][c] * wv;
                }
            }
        }
#pragma unroll
    for (int ox = 0; ox < OUTW; ox++)
        yout[((size_t)(b * OUTW + oy) * OUTW + ox) * 128 + o] = fmaxf(acc[ox], 0.f);
}
__global__ void k_conv_n2(const float* __restrict__ b) { conv_s2_body<14, 7>(g_y1, g_w2t, b, g_y2); }
__global__ void k_conv_n3(const float* __restrict__ b) { conv_s2_body<7, 4>(g_y2, g_w3t, b, g_y3); }

__global__ void k_scores(const float* __restrict__ t1w, const float* __restrict__ t1b,
                         const float* __restrict__ t2w, const float* __restrict__ t2b,
                         const float* __restrict__ t3w, const float* __restrict__ t3b) {
    int gid = blockIdx.x * 256 + threadIdx.x;
    if (gid >= 16 * ANCH_N) return;
    int b = gid / ANCH_N, r = gid - b * ANCH_N;
    const float *f, *w; float bv;
    if (r < 1176) {
        int a = r / 196, p = r - a * 196;
        f = g_y1 + (size_t)(b * 196 + p) * 128; w = t1w + a * 128; bv = t1b[a];
    } else if (r < 1470) {
        int rr = r - 1176, a = rr / 49, p = rr - a * 49;
        f = g_y2 + (size_t)(b * 49 + p) * 128; w = t2w + a * 128; bv = t2b[a];
    } else {
        int rr = r - 1470, a = rr >> 4, p = rr & 15;
        f = g_y3 + (size_t)(b * 16 + p) * 128; w = t3w + a * 128; bv = t3b[a];
    }
    float acc = bv;
#pragma unroll 4
    for (int c = 0; c < 128; c++) acc += f[c] * w[c];
    g_rpn[gid] = acc;
}

__global__ void k_nms(const int* __restrict__ an) {
    const int b = blockIdx.x, tid = threadIdx.x;
    __shared__ float sc[ANCH_N];
    __shared__ int vld[ANCH_N];
    __shared__ float rv[256];
    __shared__ int ri[256];
    __shared__ int pick;
    for (int i = tid; i < ANCH_N; i += 256) { sc[i] = g_rpn[b * ANCH_N + i]; vld[i] = 1; }
    __syncthreads();
    for (int it = 0; it < 4; it++) {
        float v = -3.0e38f; int idx = ANCH_N;
        for (int i = tid; i < ANCH_N; i += 256)
            if (vld[i]) { float sv = sc[i]; if (sv > v) { v = sv; idx = i; } }
        rv[tid] = v; ri[tid] = idx;
        __syncthreads();
        for (int st = 128; st; st >>= 1) {
            if (tid < st) {
                float v2 = rv[tid + st]; int i2 = ri[tid + st];
                if (v2 > rv[tid] || (v2 == rv[tid] && i2 < ri[tid])) { rv[tid] = v2; ri[tid] = i2; }
            }
            __syncthreads();
        }
        if (tid == 0) { pick = ri[0]; g_top[b * 4 + it] = ri[0]; }
        __syncthreads();
        int pi = pick;
        float py0 = (float)an[pi * 4], px0 = (float)an[pi * 4 + 1];
        float py1 = (float)an[pi * 4 + 2], px1 = (float)an[pi * 4 + 3];
        float pa = (py1 - py0) * (px1 - px0);
        for (int i = tid; i < ANCH_N; i += 256) {
            float y0 = (float)an[i * 4], x0 = (float)an[i * 4 + 1];
            float y1 = (float)an[i * 4 + 2], x1 = (float)an[i * 4 + 3];
            float ih = fminf(y1, py1) - fmaxf(y0, py0);
            float iw = fminf(x1, px1) - fmaxf(x0, px0);
            float inter = (ih < 0.f || iw < 0.f) ? 0.f : ih * iw;
            float iou = inter / ((y1 - y0) * (x1 - x0) + pa - inter);
            if (iou >= 0.25f) vld[i] = 0;
        }
        __syncthreads();
    }
}

__global__ void k_abar(const float* __restrict__ x, const int* __restrict__ an) {
    int gid = blockIdx.x * 256 + threadIdx.x; // 196608
    int p = gid / 3072, k = gid - p * 3072;
    int c = k >> 10, ky = (k >> 5) & 31, kx = k & 31;
    int b = p >> 2;
    int ai = g_top[p];
    int y0 = an[ai * 4], x0 = an[ai * 4 + 1], y1 = an[ai * 4 + 2], x1 = an[ai * 4 + 3];
    float hm1 = (float)(y1 - y0 - 1), wm1 = (float)(x1 - x0 - 1);
    int ix0[7], ix1[7]; float wx[7];
#pragma unroll
    for (int tj = 0; tj < 7; tj++) {
        float sx = __fdiv_rn((float)(tj * 32 + kx) * wm1, 223.f);
        float fx = floorf(sx);
        wx[tj] = sx - fx;
        int i0 = x0 + (int)fx;
        ix0[tj] = i0 - 224;
        ix1[tj] = min(i0 + 1, x1 - 1) - 224;
    }
    const float* xb = x + (size_t)(b * 3 + c) * 200704;
    float acc = 0.f;
#pragma unroll
    for (int ti = 0; ti < 7; ti++) {
        float sy = __fdiv_rn((float)(ti * 32 + ky) * hm1, 223.f);
        float fy = floorf(sy);
        float wy = sy - fy;
        int ry0 = y0 + (int)fy - 224;
        int ry1 = min(y0 + (int)fy + 1, y1 - 1) - 224;
        bool v0 = (unsigned)ry0 < 448u, v1 = (unsigned)ry1 < 448u;
#pragma unroll
        for (int tj = 0; tj < 7; tj++) {
            int cx0 = ix0[tj], cx1 = ix1[tj];
            bool u0 = (unsigned)cx0 < 448u, u1 = (unsigned)cx1 < 448u;
            float v00 = (v0 && u0) ? xb[ry0 * 448 + cx0] : 0.f;
            float v01 = (v0 && u1) ? xb[ry0 * 448 + cx1] : 0.f;
            float v10 = (v1 && u0) ? xb[ry1 * 448 + cx0] : 0.f;
            float v11 = (v1 && u1) ? xb[ry1 * 448 + cx1] : 0.f;
            float w = wx[tj];
            float top = v00 * (1.f - w) + v01 * w;
            float bot = v10 * (1.f - w) + v11 * w;
            acc += top * (1.f - wy) + bot * wy;
        }
    }
    g_abar[gid] = acc * (1.f / 49.f);
}

__device__ __forceinline__ void mac_tile(const float* As, const float* Bs,
                                         float acc[4][8], int ty, int tx) {
#pragma unroll
    for (int kk = 0; kk < 32; kk++) {
        float a0 = As[kk * 65 + ty * 4 + 0];
        float a1 = As[kk * 65 + ty * 4 + 1];
        float a2 = As[kk * 65 + ty * 4 + 2];
        float a3 = As[kk * 65 + ty * 4 + 3];
        float4 b0 = *(const float4*)&Bs[kk * 128 + tx * 8];
        float4 b1 = *(const float4*)&Bs[kk * 128 + tx * 8 + 4];
        float bv[8] = {b0.x, b0.y, b0.z, b0.w, b1.x, b1.y, b1.z, b1.w};
#pragma unroll
        for (int j = 0; j < 8; j++) {
            acc[0][j] += a0 * bv[j];
            acc[1][j] += a1 * bv[j];
            acc[2][j] += a2 * bv[j];
            acc[3][j] += a3 * bv[j];
        }
    }
}
__global__ __launch_bounds__(256, 3) void k_gemm_part() {
    __shared__ float As[32 * 65];
    __shared__ float Bs[32 * 128];
    const int tid = threadIdx.x;
    const int n0 = blockIdx.y * 128, s = blockIdx.z;
    const int kl = tid & 31, mr = tid >> 5;
    const int ty = tid >> 4, tx = tid & 15;
    float acc[4][8];
#pragma unroll
    for (int a = 0; a < 4; a++)
#pragma unroll
        for (int q = 0; q < 8; q++) acc[a][q] = 0.f;
    for (int kt = s * 12; kt < s * 12 + 12; kt++) {
#pragma unroll
        for (int l = 0; l < 8; l++)
            As[kl * 65 + mr + l * 8] = g_abar[(size_t)(mr + l * 8) * 3072 + kt * 32 + kl];
        const float* bsrc = g_bbwt + (size_t)kt * 65536 + n0;
#pragma unroll
        for (int l = 0; l < 16; l++) {
            int e = tid + l * 256;
            Bs[e] = bsrc[(e >> 7) * 2048 + (e & 127)];
        }
        __syncthreads();
        mac_tile(As, Bs, acc, ty, tx);
        __syncthreads();
    }
#pragma unroll
    for (int im = 0; im < 4; im++) {
        float* dst = g_pfp + (size_t)(s * 64 + ty * 4 + im) * 2048 + n0 + tx * 8;
#pragma unroll
        for (int jn = 0; jn < 8; jn++) dst[jn] = acc[im][jn];
    }
}
__global__ void k_reduce_part(const float* __restrict__ bb) {
    int gid = blockIdx.x * 256 + threadIdx.x; // 131072
    float v = bb[gid & 2047];
#pragma unroll
    for (int s = 0; s < 8; s++) v += g_pfp[(size_t)s * 131072 + gid];
    g_pf[gid] = v;
}
__global__ void k_rawfeat() {
    int gid = blockIdx.x * 256 + threadIdx.x; // 32768
    int b = gid >> 11, o = gid & 2047;
    float v = 0.f;
    for (int p = 0; p < 196; p++) v += g_raw[(size_t)(b * 196 + p) * 2048 + o];
    g_rf[gid] = v * (1.f / 196.f);
}
__global__ void k_classifier(const float* __restrict__ cw, const float* __restrict__ cb,
                             float* __restrict__ out) {
    int w = blockIdx.x * 8 + (threadIdx.x >> 5);
    int lane = threadIdx.x & 31;
    int b = w / 200, cls = w - b * 200;
    const float* wr = cw + (size_t)cls * 10240;
    const float* pf = g_pf + (size_t)b * 4 * 2048;
    const float* rf = g_rf + (size_t)b * 2048;
    float acc = 0.f;
    for (int j = lane; j < 8192; j += 32) acc += pf[j] * wr[j];
    for (int j = lane; j < 2048; j += 32) acc += rf[j] * wr[8192 + j];
#pragma unroll
    for (int st = 16; st; st >>= 1) acc += __shfl_xor_sync(0xffffffffu, acc, st);
    if (lane == 0) out[w] = acc + cb[cls];
}

// ================= launch =================
extern "C" void kernel_launch(void* const* d_in, const int* in_sizes, int n_in,
                              void* d_out, int out_size) {
    const float* x     = (const float*)d_in[0];
    const float* bb_w  = (const float*)d_in[1];
    const float* bb_b  = (const float*)d_in[2];
    const float* n1_dw = (const float*)d_in[3];
    const float* n1_db = (const float*)d_in[4];
    const float* n1_tw = (const float*)d_in[5];
    const float* n1_tb = (const float*)d_in[6];
    const float* n2_dw = (const float*)d_in[7];
    const float* n2_db = (const float*)d_in[8];
    const float* n2_tw = (const float*)d_in[9];
    const float* n2_tb = (const float*)d_in[10];
    const float* n3_dw = (const float*)d_in[11];
    const float* n3_db = (const float*)d_in[12];
    const float* n3_tw = (const float*)d_in[13];
    const float* n3_tb = (const float*)d_in[14];
    const float* cn_w  = (const float*)d_in[15];
    const float* cn_b  = (const float*)d_in[16];
    const int*   anch  = (const int*)d_in[17];
    float* out = (float*)d_out;

    cudaFuncSetAttribute(k_mm1, cudaFuncAttributeMaxDynamicSharedMemorySize, MM_SMEM);
    cudaFuncSetAttribute(k_mm2, cudaFuncAttributeMaxDynamicSharedMemorySize, MM_SMEM);

    // order chosen so k_mm1 is the 4th kernel launch (ncu -s window lands on it)
    k_build_a1<<<38400, 256>>>(x);
    k_build_b1<<<24576, 256>>>(bb_w);
    k_transpose_bbw<<<dim3(96, 64), dim3(32, 8)>>>(bb_w);
    k_mm1<<<dim3(25, 16), 256, MM_SMEM>>>(bb_b);
    k_build_w1b<<<9216, 256>>>(n1_dw);
    k_repack_w2<<<576, 256>>>(n2_dw);
    k_repack_w3<<<576, 256>>>(n3_dw);
    k_mm2<<<dim3(25, 1, 6), 256, MM_SMEM>>>();
    k_reduce_y1<<<1568, 256>>>(n1_db);
    k_conv_n2<<<dim3(16, 7), 128>>>(n2_db);
    k_conv_n3<<<dim3(16, 4), 128>>>(n3_db);
    k_scores<<<101, 256>>>(n1_tw, n1_tb, n2_tw, n2_tb, n3_tw, n3_tb);
    k_nms<<<16, 256>>>(anch);
    k_abar<<<768, 256>>>(x, anch);
    k_gemm_part<<<dim3(1, 16, 8), 256>>>();
    k_reduce_part<<<512, 256>>>(bb_b);
    k_rawfeat<<<128, 256>>>();
    k_classifier<<<400, 256>>>(cn_w, cn_b, out);
}